// round 13
// baseline (speedup 1.0000x reference)
#include <cuda_runtime.h>
#include <cuda_bf16.h>
#include <cstdint>
#include <cstddef>

// ---------------- problem constants ----------------
#define NVOX   196608
#define CDIM   192
#define SETS   4096
#define SETSZ  48
#define NHEAD  8
#define HD     24
#define DFF    384

// ---------------- scratch (device globals) ----------------
__device__ __nv_bfloat16 g_qkin[(size_t)NVOX * CDIM];   // gathered src+pos (set-slot order)
__device__ __nv_bfloat16 g_feat[(size_t)NVOX * CDIM];   // gathered src
__device__ __nv_bfloat16 g_qk  [(size_t)NVOX * 2 * CDIM];
__device__ __nv_bfloat16 g_v   [(size_t)NVOX * CDIM];
__device__ __nv_bfloat16 g_ctx [(size_t)NVOX * CDIM];
__device__ float         g_x   [(size_t)NVOX * CDIM];   // LN1 out, fp32 (residual precision)
__device__ __nv_bfloat16 g_xb  [(size_t)NVOX * CDIM];   // LN1 out, bf16 (FFN input)
// bf16 weights
__device__ __nv_bfloat16 g_wqkv[3 * CDIM * CDIM];
__device__ __nv_bfloat16 g_wout[CDIM * CDIM];
__device__ __nv_bfloat16 g_w1  [DFF * CDIM];
__device__ __nv_bfloat16 g_w2  [CDIM * DFF];

// ---------------- helpers ----------------
__device__ __forceinline__ uint32_t pack_bf16(float x, float y)
{
    __nv_bfloat162 h2 = __floats2bfloat162_rn(x, y);
    return *reinterpret_cast<const uint32_t*>(&h2);
}

__device__ __forceinline__ void mma_bf16(float c[4],
    uint32_t a0, uint32_t a1, uint32_t a2, uint32_t a3,
    uint32_t b0, uint32_t b1)
{
    asm volatile(
        "mma.sync.aligned.m16n8k16.row.col.f32.bf16.bf16.f32 "
        "{%0,%1,%2,%3}, {%4,%5,%6,%7}, {%8,%9}, {%0,%1,%2,%3};\n"
        : "+f"(c[0]), "+f"(c[1]), "+f"(c[2]), "+f"(c[3])
        : "r"(a0), "r"(a1), "r"(a2), "r"(a3), "r"(b0), "r"(b1));
}
__device__ __forceinline__ void ldsm_x4(uint32_t& r0, uint32_t& r1,
                                        uint32_t& r2, uint32_t& r3, uint32_t addr)
{
    asm volatile("ldmatrix.sync.aligned.m8n8.x4.shared.b16 {%0,%1,%2,%3}, [%4];"
                 : "=r"(r0), "=r"(r1), "=r"(r2), "=r"(r3) : "r"(addr));
}
__device__ __forceinline__ void ldsm_x4_t(uint32_t& r0, uint32_t& r1,
                                          uint32_t& r2, uint32_t& r3, uint32_t addr)
{
    asm volatile("ldmatrix.sync.aligned.m8n8.x4.trans.shared.b16 {%0,%1,%2,%3}, [%4];"
                 : "=r"(r0), "=r"(r1), "=r"(r2), "=r"(r3) : "r"(addr));
}
__device__ __forceinline__ void cp16(uint32_t saddr, const void* gaddr)
{
    asm volatile("cp.async.cg.shared.global [%0], [%1], 16;"
                 :: "r"(saddr), "l"(gaddr) : "memory");
}
#define CP_COMMIT() asm volatile("cp.async.commit_group;" ::: "memory")
#define CP_WAIT1()  asm volatile("cp.async.wait_group 1;" ::: "memory")
#define CP_WAIT0()  asm volatile("cp.async.wait_group 0;" ::: "memory")

// ---------------- weight fp32 -> bf16 conversion ----------------
__global__ void cvt_kernel(const float* __restrict__ in, __nv_bfloat16* __restrict__ out, int n2)
{
    int i = blockIdx.x * blockDim.x + threadIdx.x;
    if (i < n2) ((uint32_t*)out)[i] = pack_bf16(in[2 * i], in[2 * i + 1]);
}

// ---------------- gather: qkin = bf16(src[v]+pos[v]), feat = bf16(src[v]) ---
__global__ void __launch_bounds__(256)
gather_kernel(const float* __restrict__ src, const float* __restrict__ pos,
              const int* __restrict__ vidx)
{
    size_t i = (size_t)blockIdx.x * blockDim.x + threadIdx.x; // per 8 elements
    if (i >= (size_t)NVOX * (CDIM / 8)) return;
    int slot = (int)(i / (CDIM / 8));
    int c8   = (int)(i % (CDIM / 8)) * 8;
    int v = vidx[slot];
    const float4* s4 = (const float4*)(src + (size_t)v * CDIM + c8);
    const float4* p4 = (const float4*)(pos + (size_t)v * CDIM + c8);
    float4 s0 = s4[0], s1 = s4[1];
    float4 p0 = p4[0], p1 = p4[1];
    uint4 fo, qo;
    fo.x = pack_bf16(s0.x, s0.y); fo.y = pack_bf16(s0.z, s0.w);
    fo.z = pack_bf16(s1.x, s1.y); fo.w = pack_bf16(s1.z, s1.w);
    qo.x = pack_bf16(s0.x + p0.x, s0.y + p0.y); qo.y = pack_bf16(s0.z + p0.z, s0.w + p0.w);
    qo.z = pack_bf16(s1.x + p1.x, s1.y + p1.y); qo.w = pack_bf16(s1.z + p1.z, s1.w + p1.w);
    *(uint4*)(g_feat + i * 8) = fo;
    *(uint4*)(g_qkin + i * 8) = qo;
}

// ---------------- bf16 GEMM, BM=64 BN=192 BK=32, cp.async 3-stage ----------
#define STAGE_B 20480
#define OFF_B_ST 5120
#define OFF_SV_B (3 * STAGE_B)
#define GEMM_SMEM_BYTES (OFF_SV_B + 256)

template <int RELU, int EPI>
__global__ void __launch_bounds__(256, 2)
gemm_bf16(const __nv_bfloat16* __restrict__ A, const __nv_bfloat16* __restrict__ B,
          const float* __restrict__ bias,
          void* __restrict__ Cv, void* __restrict__ C2v,
          const int* __restrict__ vidx,
          const float* __restrict__ e_src,
          const float* __restrict__ e_g1, const float* __restrict__ e_b1,
          int N, int K)
{
    extern __shared__ char smem[];
    const uint32_t sbase = (uint32_t)__cvta_generic_to_shared(smem);
    int* sv = (int*)(smem + OFF_SV_B);

    const int tid  = threadIdx.x;
    const int lane = tid & 31;
    const int warp = tid >> 5;
    const int wr   = warp >> 2;
    const int wc   = warp & 3;
    const int row0 = blockIdx.x * 64;
    const int col0 = blockIdx.y * 192;

    if (EPI == 1 && tid < 64) sv[tid] = vidx[row0 + tid];

    float acc[2][6][4];
    #pragma unroll
    for (int m = 0; m < 2; m++)
        #pragma unroll
        for (int n = 0; n < 6; n++)
            #pragma unroll
            for (int i = 0; i < 4; i++) acc[m][n][i] = 0.f;

    const __nv_bfloat16* Arow = A + (size_t)row0 * K;
    const __nv_bfloat16* Brow = B + (size_t)col0 * K;
    const int arow = tid >> 2;
    const int ach  = tid & 3;

    auto issue = [&](int it) {
        int st = it % 3;
        uint32_t sA = sbase + st * STAGE_B;
        int kb = it * 32;
        cp16(sA + arow * 80 + ach * 16, Arow + (size_t)arow * K + kb + ach * 8);
        uint32_t sB = sA + OFF_B_ST;
        #pragma unroll
        for (int r = 0; r < 3; r++) {
            int rr = arow + r * 64;
            cp16(sB + rr * 80 + ach * 16, Brow + (size_t)rr * K + kb + ach * 8);
        }
        CP_COMMIT();
    };

    const int a_row = wr * 32 + (lane & 7) + ((lane >> 3) & 1) * 8;
    const int a_cb  = ((lane >> 4) & 1) * 4;
    const int b_row = wc * 48 + (lane & 7) + ((lane >> 4) & 1) * 8;
    const int b_cb  = ((lane >> 3) & 1) * 4;

    const int nk = K >> 5;
    issue(0); issue(1);

    for (int it = 0; it < nk; it++) {
        CP_WAIT1();
        __syncthreads();
        if (it + 2 < nk) issue(it + 2);
        else CP_COMMIT();

        const int st = it % 3;
        const uint32_t stA = sbase + st * STAGE_B;
        const uint32_t stB = stA + OFF_B_ST;
        #pragma unroll
        for (int k16 = 0; k16 < 2; k16++) {
            const int kp = k16 * 8;
            uint32_t ah[4], ah2[4];
            ldsm_x4(ah[0], ah[1], ah[2], ah[3],
                    stA + (uint32_t)((a_row * 20 + kp + a_cb) * 4));
            ldsm_x4(ah2[0], ah2[1], ah2[2], ah2[3],
                    stA + (uint32_t)(((a_row + 16) * 20 + kp + a_cb) * 4));
            uint32_t bh[12];
            #pragma unroll
            for (int p = 0; p < 3; p++) {
                ldsm_x4(bh[p * 4 + 0], bh[p * 4 + 1], bh[p * 4 + 2], bh[p * 4 + 3],
                        stB + (uint32_t)(((b_row + p * 16) * 20 + kp + b_cb) * 4));
            }
            #pragma unroll
            for (int nt = 0; nt < 6; nt++) {
                uint32_t bh0 = bh[nt * 2], bh1 = bh[nt * 2 + 1];
                mma_bf16(acc[0][nt], ah[0],  ah[1],  ah[2],  ah[3],  bh0, bh1);
                mma_bf16(acc[1][nt], ah2[0], ah2[1], ah2[2], ah2[3], bh0, bh1);
            }
        }
        __syncthreads();
    }

    // ================= epilogue =================
    if (EPI == 0) {
        __nv_bfloat16* Cb = (__nv_bfloat16*)Cv;
        #pragma unroll
        for (int mt = 0; mt < 2; mt++) {
            int r0 = row0 + wr * 32 + mt * 16 + (lane >> 2);
            #pragma unroll
            for (int nt = 0; nt < 6; nt++) {
                int c = col0 + wc * 48 + nt * 8 + 2 * (lane & 3);
                float bx = bias[c], by = bias[c + 1];
                float o0x = acc[mt][nt][0] + bx, o0y = acc[mt][nt][1] + by;
                float o1x = acc[mt][nt][2] + bx, o1y = acc[mt][nt][3] + by;
                if (RELU) {
                    o0x = fmaxf(o0x, 0.f); o0y = fmaxf(o0y, 0.f);
                    o1x = fmaxf(o1x, 0.f); o1y = fmaxf(o1y, 0.f);
                }
                *(uint32_t*)&Cb[(size_t)r0 * N + c]       = pack_bf16(o0x, o0y);
                *(uint32_t*)&Cb[(size_t)(r0 + 8) * N + c] = pack_bf16(o1x, o1y);
            }
        }
        return;
    }

    // EPI == 1: LN1 scatter (N == 192, col0 == 0)
    float* rsum = (float*)smem;
    float* rsq  = (float*)smem + 64;
    if (tid < 64) { rsum[tid] = 0.f; rsq[tid] = 0.f; }
    __syncthreads();

    #pragma unroll
    for (int mt = 0; mt < 2; mt++) {
        #pragma unroll
        for (int half = 0; half < 2; half++) {
            int row = wr * 32 + mt * 16 + (lane >> 2) + half * 8;
            float s1 = 0.f, s2 = 0.f;
            #pragma unroll
            for (int nt = 0; nt < 6; nt++) {
                int c = wc * 48 + nt * 8 + 2 * (lane & 3);
                int v = sv[row];
                float2 res = *(const float2*)&e_src[(size_t)v * CDIM + c];
                float v0 = acc[mt][nt][half * 2 + 0] + bias[c]     + res.x;
                float v1 = acc[mt][nt][half * 2 + 1] + bias[c + 1] + res.y;
                acc[mt][nt][half * 2 + 0] = v0;
                acc[mt][nt][half * 2 + 1] = v1;
                s1 += v0 + v1; s2 += v0 * v0 + v1 * v1;
            }
            atomicAdd(&rsum[row], s1);
            atomicAdd(&rsq[row],  s2);
        }
    }
    __syncthreads();

    {
        float* Cf = (float*)Cv;
        __nv_bfloat16* Cb2 = (__nv_bfloat16*)C2v;
        #pragma unroll
        for (int mt = 0; mt < 2; mt++) {
            #pragma unroll
            for (int half = 0; half < 2; half++) {
                int row = wr * 32 + mt * 16 + (lane >> 2) + half * 8;
                int v = sv[row];
                float mean = rsum[row] * (1.f / CDIM);
                float var  = rsq[row] * (1.f / CDIM) - mean * mean;
                float inv  = rsqrtf(var + 1e-5f);
                #pragma unroll
                for (int nt = 0; nt < 6; nt++) {
                    int c = wc * 48 + nt * 8 + 2 * (lane & 3);
                    float ox = (acc[mt][nt][half * 2 + 0] - mean) * inv * e_g1[c]     + e_b1[c];
                    float oy = (acc[mt][nt][half * 2 + 1] - mean) * inv * e_g1[c + 1] + e_b1[c + 1];
                    float2 o; o.x = ox; o.y = oy;
                    *(float2*)&Cf[(size_t)v * CDIM + c] = o;
                    *(uint32_t*)&Cb2[(size_t)v * CDIM + c] = pack_bf16(ox, oy);
                }
            }
        }
    }
}

// ---------------- fused FFN: h=relu(x@W1+b1); t=LN2(h@W2+b2+x); out=LN3(t+src)
// smem: XS 6 chunks (64x80B) | HS 12 chunks | WS 3 stages (192x80B each)
#define FF_XS 0
#define FF_HS 30720
#define FF_WS 92160
#define FF_WSTG 15360
#define FF_SMEM (FF_WS + 3 * FF_WSTG + 256)   // 138496

__global__ void __launch_bounds__(256, 1)
ffn_fused(const __nv_bfloat16* __restrict__ xb,
          const __nv_bfloat16* __restrict__ w1, const float* __restrict__ b1,
          const __nv_bfloat16* __restrict__ w2, const float* __restrict__ b2,
          float* __restrict__ outp,
          const float* __restrict__ e_src, const float* __restrict__ e_x,
          const float* __restrict__ ln2g, const float* __restrict__ ln2b,
          const float* __restrict__ ln3g, const float* __restrict__ ln3b)
{
    extern __shared__ char smem[];
    const uint32_t sbase = (uint32_t)__cvta_generic_to_shared(smem);
    const int tid  = threadIdx.x;
    const int lane = tid & 31;
    const int warp = tid >> 5;
    const int wr   = warp >> 2;
    const int wc   = warp & 3;
    const int row0 = blockIdx.x * 64;

    const int arow = tid >> 2;
    const int ach  = tid & 3;

    // ---- load xb block into XS (ldmatrix chunk layout) ----
    #pragma unroll
    for (int c = 0; c < 6; c++)
        cp16(sbase + FF_XS + c * 5120 + arow * 80 + ach * 16,
             xb + (size_t)(row0 + arow) * CDIM + c * 32 + ach * 8);
    CP_COMMIT();
    CP_WAIT0();
    __syncthreads();

    const int a_row = wr * 32 + (lane & 7) + ((lane >> 3) & 1) * 8;
    const int a_cb  = ((lane >> 4) & 1) * 4;
    const int b_row = wc * 48 + (lane & 7) + ((lane >> 4) & 1) * 8;
    const int b_cb  = ((lane >> 3) & 1) * 4;

    // ================= phase 1: H = relu(X @ W1^T + b1) =================
    #pragma unroll 1
    for (int half = 0; half < 2; half++) {
        const __nv_bfloat16* W = w1 + (size_t)half * 192 * CDIM;
        auto issueW = [&](int kc) {
            uint32_t sW = sbase + FF_WS + (kc % 3) * FF_WSTG;
            #pragma unroll
            for (int r = 0; r < 3; r++) {
                int rr = arow + r * 64;
                cp16(sW + rr * 80 + ach * 16, W + (size_t)rr * CDIM + kc * 32 + ach * 8);
            }
            CP_COMMIT();
        };
        issueW(0); issueW(1);

        float acc[2][6][4];
        #pragma unroll
        for (int m = 0; m < 2; m++)
            #pragma unroll
            for (int n = 0; n < 6; n++)
                #pragma unroll
                for (int i = 0; i < 4; i++) acc[m][n][i] = 0.f;

        for (int kc = 0; kc < 6; kc++) {
            CP_WAIT1();
            __syncthreads();
            if (kc + 2 < 6) issueW(kc + 2);
            else CP_COMMIT();

            const uint32_t stA = sbase + FF_XS + kc * 5120;
            const uint32_t stB = sbase + FF_WS + (kc % 3) * FF_WSTG;
            #pragma unroll
            for (int k16 = 0; k16 < 2; k16++) {
                const int kp = k16 * 8;
                uint32_t ah[4], ah2[4];
                ldsm_x4(ah[0], ah[1], ah[2], ah[3],
                        stA + (uint32_t)((a_row * 20 + kp + a_cb) * 4));
                ldsm_x4(ah2[0], ah2[1], ah2[2], ah2[3],
                        stA + (uint32_t)(((a_row + 16) * 20 + kp + a_cb) * 4));
                uint32_t bh[12];
                #pragma unroll
                for (int p = 0; p < 3; p++) {
                    ldsm_x4(bh[p * 4 + 0], bh[p * 4 + 1], bh[p * 4 + 2], bh[p * 4 + 3],
                            stB + (uint32_t)(((b_row + p * 16) * 20 + kp + b_cb) * 4));
                }
                #pragma unroll
                for (int nt = 0; nt < 6; nt++) {
                    uint32_t bh0 = bh[nt * 2], bh1 = bh[nt * 2 + 1];
                    mma_bf16(acc[0][nt], ah[0],  ah[1],  ah[2],  ah[3],  bh0, bh1);
                    mma_bf16(acc[1][nt], ah2[0], ah2[1], ah2[2], ah2[3], bh0, bh1);
                }
            }
            __syncthreads();
        }

        // relu + bias -> HS (bf16, chunk layout)
        #pragma unroll
        for (int mt = 0; mt < 2; mt++) {
            #pragma unroll
            for (int half2 = 0; half2 < 2; half2++) {
                int row = wr * 32 + mt * 16 + (lane >> 2) + half2 * 8;
                #pragma unroll
                for (int nt = 0; nt < 6; nt++) {
                    int col = half * 192 + wc * 48 + nt * 8 + 2 * (lane & 3);
                    float h0 = fmaxf(acc[mt][nt][half2 * 2 + 0] + b1[col], 0.f);
                    float h1 = fmaxf(acc[mt][nt][half2 * 2 + 1] + b1[col + 1], 0.f);
                    *(uint32_t*)(smem + FF_HS + (col >> 5) * 5120 + row * 80 + (col & 31) * 2)
                        = pack_bf16(h0, h1);
                }
            }
        }
    }
    __syncthreads();

    // ================= phase 2: acc = H @ W2^T =================
    auto issueW2 = [&](int kc) {
        uint32_t sW = sbase + FF_WS + (kc % 3) * FF_WSTG;
        #pragma unroll
        for (int r = 0; r < 3; r++) {
            int rr = arow + r * 64;
            cp16(sW + rr * 80 + ach * 16, w2 + (size_t)rr * DFF + kc * 32 + ach * 8);
        }
        CP_COMMIT();
    };
    issueW2(0); issueW2(1);

    float acc[2][6][4];
    #pragma unroll
    for (int m = 0; m < 2; m++)
        #pragma unroll
        for (int n = 0; n < 6; n++)
            #pragma unroll
            for (int i = 0; i < 4; i++) acc[m][n][i] = 0.f;

    for (int kc = 0; kc < 12; kc++) {
        CP_WAIT1();
        __syncthreads();
        if (kc + 2 < 12) issueW2(kc + 2);
        else CP_COMMIT();

        const uint32_t stA = sbase + FF_HS + kc * 5120;
        const uint32_t stB = sbase + FF_WS + (kc % 3) * FF_WSTG;
        #pragma unroll
        for (int k16 = 0; k16 < 2; k16++) {
            const int kp = k16 * 8;
            uint32_t ah[4], ah2[4];
            ldsm_x4(ah[0], ah[1], ah[2], ah[3],
                    stA + (uint32_t)((a_row * 20 + kp + a_cb) * 4));
            ldsm_x4(ah2[0], ah2[1], ah2[2], ah2[3],
                    stA + (uint32_t)(((a_row + 16) * 20 + kp + a_cb) * 4));
            uint32_t bh[12];
            #pragma unroll
            for (int p = 0; p < 3; p++) {
                ldsm_x4(bh[p * 4 + 0], bh[p * 4 + 1], bh[p * 4 + 2], bh[p * 4 + 3],
                        stB + (uint32_t)(((b_row + p * 16) * 20 + kp + b_cb) * 4));
            }
            #pragma unroll
            for (int nt = 0; nt < 6; nt++) {
                uint32_t bh0 = bh[nt * 2], bh1 = bh[nt * 2 + 1];
                mma_bf16(acc[0][nt], ah[0],  ah[1],  ah[2],  ah[3],  bh0, bh1);
                mma_bf16(acc[1][nt], ah2[0], ah2[1], ah2[2], ah2[3], bh0, bh1);
            }
        }
        __syncthreads();
    }

    // ---- LN2(acc + b2 + x) -> + src -> LN3 -> out (fp32) ----
    float* rsum = (float*)smem;        // XS region is free now
    float* rsq  = (float*)smem + 64;
    if (tid < 64) { rsum[tid] = 0.f; rsq[tid] = 0.f; }
    __syncthreads();

    #pragma unroll
    for (int mt = 0; mt < 2; mt++) {
        #pragma unroll
        for (int half = 0; half < 2; half++) {
            int row = wr * 32 + mt * 16 + (lane >> 2) + half * 8;
            float s1 = 0.f, s2 = 0.f;
            #pragma unroll
            for (int nt = 0; nt < 6; nt++) {
                int c = wc * 48 + nt * 8 + 2 * (lane & 3);
                float2 res = *(const float2*)&e_x[(size_t)(row0 + row) * CDIM + c];
                float v0 = acc[mt][nt][half * 2 + 0] + b2[c]     + res.x;
                float v1 = acc[mt][nt][half * 2 + 1] + b2[c + 1] + res.y;
                acc[mt][nt][half * 2 + 0] = v0;
                acc[mt][nt][half * 2 + 1] = v1;
                s1 += v0 + v1; s2 += v0 * v0 + v1 * v1;
            }
            atomicAdd(&rsum[row], s1);
            atomicAdd(&rsq[row],  s2);
        }
    }
    __syncthreads();

    float su1[4], su2[4];
    #pragma unroll
    for (int mt = 0; mt < 2; mt++) {
        #pragma unroll
        for (int half = 0; half < 2; half++) {
            int row = wr * 32 + mt * 16 + (lane >> 2) + half * 8;
            float mean = rsum[row] * (1.f / CDIM);
            float var  = rsq[row] * (1.f / CDIM) - mean * mean;
            float inv  = rsqrtf(var + 1e-5f);
            float s1 = 0.f, s2 = 0.f;
            #pragma unroll
            for (int nt = 0; nt < 6; nt++) {
                int c = wc * 48 + nt * 8 + 2 * (lane & 3);
                float2 sr = *(const float2*)&e_src[(size_t)(row0 + row) * CDIM + c];
                float u0 = (acc[mt][nt][half * 2 + 0] - mean) * inv * ln2g[c]     + ln2b[c]     + sr.x;
                float u1 = (acc[mt][nt][half * 2 + 1] - mean) * inv * ln2g[c + 1] + ln2b[c + 1] + sr.y;
                acc[mt][nt][half * 2 + 0] = u0;
                acc[mt][nt][half * 2 + 1] = u1;
                s1 += u0 + u1; s2 += u0 * u0 + u1 * u1;
            }
            su1[mt * 2 + half] = s1;
            su2[mt * 2 + half] = s2;
        }
    }
    __syncthreads();
    if (tid < 64) { rsum[tid] = 0.f; rsq[tid] = 0.f; }
    __syncthreads();
    #pragma unroll
    for (int mt = 0; mt < 2; mt++) {
        #pragma unroll
        for (int half = 0; half < 2; half++) {
            int row = wr * 32 + mt * 16 + (lane >> 2) + half * 8;
            atomicAdd(&rsum[row], su1[mt * 2 + half]);
            atomicAdd(&rsq[row],  su2[mt * 2 + half]);
        }
    }
    __syncthreads();
    #pragma unroll
    for (int mt = 0; mt < 2; mt++) {
        #pragma unroll
        for (int half = 0; half < 2; half++) {
            int row = wr * 32 + mt * 16 + (lane >> 2) + half * 8;
            float mean = rsum[row] * (1.f / CDIM);
            float var  = rsq[row] * (1.f / CDIM) - mean * mean;
            float inv  = rsqrtf(var + 1e-5f);
            #pragma unroll
            for (int nt = 0; nt < 6; nt++) {
                int c = wc * 48 + nt * 8 + 2 * (lane & 3);
                float2 o;
                o.x = (acc[mt][nt][half * 2 + 0] - mean) * inv * ln3g[c]     + ln3b[c];
                o.y = (acc[mt][nt][half * 2 + 1] - mean) * inv * ln3g[c + 1] + ln3b[c + 1];
                *(float2*)&outp[(size_t)(row0 + row) * CDIM + c] = o;
            }
        }
    }
}

// ---------------- attention (tensor-core): 192 thr = 2 pairs x 3 warps ------
__global__ void __launch_bounds__(192)
attn_kernel(const uint8_t* __restrict__ mask)
{
    __shared__ __nv_bfloat16 qs[2][SETSZ][40];
    __shared__ __nv_bfloat16 ks[2][SETSZ][40];
    __shared__ __nv_bfloat16 vs[2][SETSZ][40];
    __shared__ float mf[2][SETSZ];

    const int tid  = threadIdx.x;
    const int lane = tid & 31;
    const int warp = tid >> 5;
    const int p    = warp / 3;
    const int w    = warp % 3;

    {
        int lt = tid % 96;
        int pp = tid / 96;
        int gpp = blockIdx.x * 2 + pp;
        int ss = gpp >> 3, hh = gpp & 7;
        for (int task = lt; task < SETSZ * 3; task += 96) {
            int row = task / 3, ch = task % 3;
            size_t ro = (size_t)ss * SETSZ + row;
            const __nv_bfloat16* qrow = g_qk + ro * (2 * CDIM) + (size_t)hh * HD + ch * 8;
            *(uint4*)&qs[pp][row][ch * 8] = *(const uint4*)qrow;
            *(uint4*)&ks[pp][row][ch * 8] = *(const uint4*)(qrow + CDIM);
            *(uint4*)&vs[pp][row][ch * 8] = *(const uint4*)(g_v + ro * CDIM + (size_t)hh * HD + ch * 8);
        }
        for (int row = lt; row < SETSZ; row += 96) {
            *(uint4*)&qs[pp][row][24] = make_uint4(0, 0, 0, 0);
            *(uint4*)&ks[pp][row][24] = make_uint4(0, 0, 0, 0);
            *(uint4*)&vs[pp][row][24] = make_uint4(0, 0, 0, 0);
            mf[pp][row] = (mask[(size_t)ss * SETSZ + row] != 0) ? -1e9f : 0.f;
        }
    }
    __syncthreads();

    const int gp = blockIdx.x * 2 + p;
    const int s  = gp >> 3;
    const int h  = gp & 7;

    const uint32_t sq = (uint32_t)__cvta_generic_to_shared(&qs[p][0][0]);
    const uint32_t sk = (uint32_t)__cvta_generic_to_shared(&ks[p][0][0]);
    const uint32_t svv = (uint32_t)__cvta_generic_to_shared(&vs[p][0][0]);

    const int a_row = w * 16 + (lane & 7) + ((lane >> 3) & 1) * 8;
    const int a_cb  = ((lane >> 4) & 1) * 4;
    const int b_row = (lane & 7) + ((lane >> 4) & 1) * 8;
    const int b_cb  = ((lane >> 3) & 1) * 4;

    float sacc[6][4];
    #pragma unroll
    for (int nt = 0; nt < 6; nt++)
        #pragma unroll
        for (int i = 0; i < 4; i++) sacc[nt][i] = 0.f;

    #pragma unroll
    for (int kt = 0; kt < 2; kt++) {
        uint32_t qa[4];
        ldsm_x4(qa[0], qa[1], qa[2], qa[3],
                sq + (uint32_t)((a_row * 20 + kt * 8 + a_cb) * 4));
        uint32_t kb[12];
        #pragma unroll
        for (int t = 0; t < 3; t++)
            ldsm_x4(kb[t * 4 + 0], kb[t * 4 + 1], kb[t * 4 + 2], kb[t * 4 + 3],
                    sk + (uint32_t)(((b_row + t * 16) * 20 + kt * 8 + b_cb) * 4));
        #pragma unroll
        for (int nt = 0; nt < 6; nt++)
            mma_bf16(sacc[nt], qa[0], qa[1], qa[2], qa[3], kb[nt * 2], kb[nt * 2 + 1]);
    }

    const float scale = 0.20412414523193154f;
    float m0 = -1e30f, m1 = -1e30f;
    #pragma unroll
    for (int nt = 0; nt < 6; nt++) {
        int j0 = nt * 8 + (lane & 3) * 2;
        float mv0 = mf[p][j0], mv1 = mf[p][j0 + 1];
        sacc[nt][0] = sacc[nt][0] * scale + mv0;
        sacc[nt][1] = sacc[nt][1] * scale + mv1;
        sacc[nt][2] = sacc[nt][2] * scale + mv0;
        sacc[nt][3] = sacc[nt][3] * scale + mv1;
        m0 = fmaxf(m0, fmaxf(sacc[nt][0], sacc[nt][1]));
        m1 = fmaxf(m1, fmaxf(sacc[nt][2], sacc[nt][3]));
    }
    m0 = fmaxf(m0, __shfl_xor_sync(0xFFFFFFFFu, m0, 1));
    m0 = fmaxf(m0, __shfl_xor_sync(0xFFFFFFFFu, m0, 2));
    m1 = fmaxf(m1, __shfl_xor_sync(0xFFFFFFFFu, m1, 1));
    m1 = fmaxf(m1, __shfl_xor_sync(0xFFFFFFFFu, m1, 2));
    float s0 = 0.f, s1 = 0.f;
    #pragma unroll
    for (int nt = 0; nt < 6; nt++) {
        sacc[nt][0] = __expf(sacc[nt][0] - m0);
        sacc[nt][1] = __expf(sacc[nt][1] - m0);
        sacc[nt][2] = __expf(sacc[nt][2] - m1);
        sacc[nt][3] = __expf(sacc[nt][3] - m1);
        s0 += sacc[nt][0] + sacc[nt][1];
        s1 += sacc[nt][2] + sacc[nt][3];
    }
    s0 += __shfl_xor_sync(0xFFFFFFFFu, s0, 1);
    s0 += __shfl_xor_sync(0xFFFFFFFFu, s0, 2);
    s1 += __shfl_xor_sync(0xFFFFFFFFu, s1, 1);
    s1 += __shfl_xor_sync(0xFFFFFFFFu, s1, 2);
    float i0 = 1.f / s0, i1 = 1.f / s1;
    #pragma unroll
    for (int nt = 0; nt < 6; nt++) {
        sacc[nt][0] *= i0; sacc[nt][1] *= i0;
        sacc[nt][2] *= i1; sacc[nt][3] *= i1;
    }

    uint32_t pah[3][4], pal[3][4];
    #pragma unroll
    for (int kt = 0; kt < 3; kt++) {
        const float* t0 = sacc[2 * kt];
        const float* t1 = sacc[2 * kt + 1];
        float src4[4][2] = {{t0[0], t0[1]}, {t0[2], t0[3]}, {t1[0], t1[1]}, {t1[2], t1[3]}};
        #pragma unroll
        for (int r = 0; r < 4; r++) {
            __nv_bfloat162 hh = __floats2bfloat162_rn(src4[r][0], src4[r][1]);
            pah[kt][r] = *reinterpret_cast<const uint32_t*>(&hh);
            float lx = src4[r][0] - __bfloat162float(hh.x);
            float ly = src4[r][1] - __bfloat162float(hh.y);
            pal[kt][r] = pack_bf16(lx, ly);
        }
    }

    float oacc[3][4];
    #pragma unroll
    for (int d = 0; d < 3; d++)
        #pragma unroll
        for (int i = 0; i < 4; i++) oacc[d][i] = 0.f;

    const int v_row = (lane & 7) + ((lane >> 3) & 1) * 8;
    const int v_cb  = ((lane >> 4) & 1) * 4;
    #pragma unroll
    for (int kt = 0; kt < 3; kt++) {
        uint32_t base = svv + (uint32_t)(((16 * kt + v_row) * 20 + v_cb) * 4);
        uint32_t b0[4], b1[4];
        ldsm_x4_t(b0[0], b0[1], b0[2], b0[3], base);
        ldsm_x4_t(b1[0], b1[1], b1[2], b1[3], base + 32);
        mma_bf16(oacc[0], pah[kt][0], pah[kt][1], pah[kt][2], pah[kt][3], b0[0], b0[1]);
        mma_bf16(oacc[0], pal[kt][0], pal[kt][1], pal[kt][2], pal[kt][3], b0[0], b0[1]);
        mma_bf16(oacc[1], pah[kt][0], pah[kt][1], pah[kt][2], pah[kt][3], b0[2], b0[3]);
        mma_bf16(oacc[1], pal[kt][0], pal[kt][1], pal[kt][2], pal[kt][3], b0[2], b0[3]);
        mma_bf16(oacc[2], pah[kt][0], pah[kt][1], pah[kt][2], pah[kt][3], b1[0], b1[1]);
        mma_bf16(oacc[2], pal[kt][0], pal[kt][1], pal[kt][2], pal[kt][3], b1[0], b1[1]);
    }

    {
        size_t r0 = (size_t)s * SETSZ + w * 16 + (lane >> 2);
        int dbase = h * HD + (lane & 3) * 2;
        #pragma unroll
        for (int db = 0; db < 3; db++) {
            int dd = dbase + db * 8;
            *(uint32_t*)&g_ctx[r0 * CDIM + dd]       = pack_bf16(oacc[db][0], oacc[db][1]);
            *(uint32_t*)&g_ctx[(r0 + 8) * CDIM + dd] = pack_bf16(oacc[db][2], oacc[db][3]);
        }
    }
}

// ---------------- launch --------------------------------------------------
extern "C" void kernel_launch(void* const* d_in, const int* in_sizes, int n_in,
                              void* d_out, int out_size)
{
    const float* src   = (const float*)d_in[0];
    const float* pos   = (const float*)d_in[1];
    const float* w_qkv = (const float*)d_in[2];
    const float* b_qkv = (const float*)d_in[3];
    const float* w_out = (const float*)d_in[4];
    const float* b_out = (const float*)d_in[5];
    const float* w1    = (const float*)d_in[6];
    const float* b1    = (const float*)d_in[7];
    const float* w2    = (const float*)d_in[8];
    const float* b2    = (const float*)d_in[9];
    const float* ln1g  = (const float*)d_in[10];
    const float* ln1b  = (const float*)d_in[11];
    const float* ln2g  = (const float*)d_in[12];
    const float* ln2b  = (const float*)d_in[13];
    const float* ln3g  = (const float*)d_in[14];
    const float* ln3b  = (const float*)d_in[15];
    const int*   vidx  = (const int*)d_in[16];
    const uint8_t* msk = (const uint8_t*)d_in[17];
    float* out = (float*)d_out;

    __nv_bfloat16 *p_qkin, *p_feat, *p_qk, *p_v, *p_ctx, *p_xb;
    __nv_bfloat16 *p_wqkv, *p_wout, *p_w1, *p_w2;
    float *p_x;
    cudaGetSymbolAddress((void**)&p_qkin, g_qkin);
    cudaGetSymbolAddress((void**)&p_feat, g_feat);
    cudaGetSymbolAddress((void**)&p_qk,   g_qk);
    cudaGetSymbolAddress((void**)&p_v,    g_v);
    cudaGetSymbolAddress((void**)&p_ctx,  g_ctx);
    cudaGetSymbolAddress((void**)&p_x,    g_x);
    cudaGetSymbolAddress((void**)&p_xb,   g_xb);
    cudaGetSymbolAddress((void**)&p_wqkv, g_wqkv);
    cudaGetSymbolAddress((void**)&p_wout, g_wout);
    cudaGetSymbolAddress((void**)&p_w1,   g_w1);
    cudaGetSymbolAddress((void**)&p_w2,   g_w2);

    cudaFuncSetAttribute(gemm_bf16<0,0>, cudaFuncAttributeMaxDynamicSharedMemorySize, GEMM_SMEM_BYTES);
    cudaFuncSetAttribute(gemm_bf16<0,1>, cudaFuncAttributeMaxDynamicSharedMemorySize, GEMM_SMEM_BYTES);
    cudaFuncSetAttribute(ffn_fused, cudaFuncAttributeMaxDynamicSharedMemorySize, FF_SMEM);

    // 0) weights -> bf16
    cvt_kernel<<<(3*CDIM*CDIM/2 + 255)/256, 256>>>(w_qkv, p_wqkv, 3*CDIM*CDIM/2);
    cvt_kernel<<<(CDIM*CDIM/2   + 255)/256, 256>>>(w_out, p_wout, CDIM*CDIM/2);
    cvt_kernel<<<(DFF*CDIM/2    + 255)/256, 256>>>(w1,    p_w1,   DFF*CDIM/2);
    cvt_kernel<<<(CDIM*DFF/2    + 255)/256, 256>>>(w2,    p_w2,   CDIM*DFF/2);

    // 1) gather (bf16)
    gather_kernel<<<(int)(((size_t)NVOX*(CDIM/8) + 255)/256), 256>>>(src, pos, vidx);

    const int MB = NVOX / 64;  // 3072

    // 2) q,k projection: (N x 384)
    gemm_bf16<0,0><<<dim3(MB, 2), 256, GEMM_SMEM_BYTES>>>(
        p_qkin, p_wqkv, b_qkv, p_qk, nullptr, nullptr,
        nullptr, nullptr, nullptr,
        2 * CDIM, CDIM);

    // 3) v projection: (N x 192)
    gemm_bf16<0,0><<<dim3(MB, 1), 256, GEMM_SMEM_BYTES>>>(
        p_feat, p_wqkv + (size_t)2 * CDIM * CDIM, b_qkv + 2 * CDIM, p_v, nullptr, nullptr,
        nullptr, nullptr, nullptr,
        CDIM, CDIM);

    // 4) attention (tensor cores)
    attn_kernel<<<(SETS * NHEAD) / 2, 192>>>(msk);

    // 5) out-proj + scatter + residual + LN1 -> g_x (fp32) + g_xb (bf16)
    gemm_bf16<0,1><<<dim3(MB, 1), 256, GEMM_SMEM_BYTES>>>(
        p_ctx, p_wout, b_out, p_x, p_xb, vidx,
        src, ln1g, ln1b,
        CDIM, CDIM);

    // 6) fused FFN1 + FFN2 + LN2 + residual + LN3 -> out (fp32)
    ffn_fused<<<MB, 256, FF_SMEM>>>(
        p_xb, p_w1, b1, p_w2, b2, out,
        src, p_x, ln2g, ln2b, ln3g, ln3b);
}

// round 14
// speedup vs baseline: 1.0900x; 1.0900x over previous
#include <cuda_runtime.h>
#include <cuda_bf16.h>
#include <cstdint>
#include <cstddef>

// ---------------- problem constants ----------------
#define NVOX   196608
#define CDIM   192
#define SETS   4096
#define SETSZ  48
#define NHEAD  8
#define HD     24
#define DFF    384

// ---------------- scratch (device globals) ----------------
__device__ __nv_bfloat16 g_qk [(size_t)NVOX * 2 * CDIM]; // q cols 0..191, k 192..383
__device__ __nv_bfloat16 g_v  [(size_t)NVOX * CDIM];
__device__ __nv_bfloat16 g_ctx[(size_t)NVOX * CDIM];
__device__ float         g_x  [(size_t)NVOX * CDIM];     // LN1 out, fp32
__device__ __nv_bfloat16 g_xb [(size_t)NVOX * CDIM];     // LN1 out, bf16
__device__ __nv_bfloat16 g_h  [(size_t)NVOX * DFF];
// bf16 weights
__device__ __nv_bfloat16 g_wqkv[3 * CDIM * CDIM];
__device__ __nv_bfloat16 g_wout[CDIM * CDIM];
__device__ __nv_bfloat16 g_w1  [DFF * CDIM];
__device__ __nv_bfloat16 g_w2  [CDIM * DFF];

// ---------------- helpers ----------------
__device__ __forceinline__ uint32_t pack_bf16(float x, float y)
{
    __nv_bfloat162 h2 = __floats2bfloat162_rn(x, y);
    return *reinterpret_cast<const uint32_t*>(&h2);
}

__device__ __forceinline__ void mma_bf16(float c[4],
    uint32_t a0, uint32_t a1, uint32_t a2, uint32_t a3,
    uint32_t b0, uint32_t b1)
{
    asm volatile(
        "mma.sync.aligned.m16n8k16.row.col.f32.bf16.bf16.f32 "
        "{%0,%1,%2,%3}, {%4,%5,%6,%7}, {%8,%9}, {%0,%1,%2,%3};\n"
        : "+f"(c[0]), "+f"(c[1]), "+f"(c[2]), "+f"(c[3])
        : "r"(a0), "r"(a1), "r"(a2), "r"(a3), "r"(b0), "r"(b1));
}
__device__ __forceinline__ void ldsm_x4(uint32_t& r0, uint32_t& r1,
                                        uint32_t& r2, uint32_t& r3, uint32_t addr)
{
    asm volatile("ldmatrix.sync.aligned.m8n8.x4.shared.b16 {%0,%1,%2,%3}, [%4];"
                 : "=r"(r0), "=r"(r1), "=r"(r2), "=r"(r3) : "r"(addr));
}
__device__ __forceinline__ void ldsm_x4_t(uint32_t& r0, uint32_t& r1,
                                          uint32_t& r2, uint32_t& r3, uint32_t addr)
{
    asm volatile("ldmatrix.sync.aligned.m8n8.x4.trans.shared.b16 {%0,%1,%2,%3}, [%4];"
                 : "=r"(r0), "=r"(r1), "=r"(r2), "=r"(r3) : "r"(addr));
}
__device__ __forceinline__ void cp16(uint32_t saddr, const void* gaddr)
{
    asm volatile("cp.async.cg.shared.global [%0], [%1], 16;"
                 :: "r"(saddr), "l"(gaddr) : "memory");
}
#define CP_COMMIT() asm volatile("cp.async.commit_group;" ::: "memory")
#define CP_WAIT1()  asm volatile("cp.async.wait_group 1;" ::: "memory")

// ---------------- weight fp32 -> bf16 conversion ----------------
__global__ void cvt_kernel(const float* __restrict__ in, __nv_bfloat16* __restrict__ out, int n2)
{
    int i = blockIdx.x * blockDim.x + threadIdx.x;
    if (i < n2) ((uint32_t*)out)[i] = pack_bf16(in[2 * i], in[2 * i + 1]);
}

// ---------------- fused gather + QKV projection ----------------------------
// Per block: 64 set-slot rows. Gathers src[v](+pos[v]) -> bf16 smem chunks,
// then 3 GEMM groups (Wq,Wk from XQ; Wv from XV), weights cp.async 3-stage.
#define QK_XQ 0
#define QK_XV 30720
#define QK_WS 61440
#define QK_WSTG 15360
#define QK_SV (QK_WS + 3 * QK_WSTG)     // 107520
#define QK_SMEM (QK_SV + 256)

__global__ void __launch_bounds__(256, 1)
qkv_fused(const float* __restrict__ src, const float* __restrict__ pos,
          const int* __restrict__ vidx,
          const __nv_bfloat16* __restrict__ wqkv, const float* __restrict__ bqkv)
{
    extern __shared__ char smem[];
    const uint32_t sbase = (uint32_t)__cvta_generic_to_shared(smem);
    int* sv = (int*)(smem + QK_SV);

    const int tid  = threadIdx.x;
    const int lane = tid & 31;
    const int warp = tid >> 5;
    const int wr   = warp >> 2;
    const int wc   = warp & 3;
    const int row0 = blockIdx.x * 64;

    if (tid < 64) sv[tid] = vidx[row0 + tid];
    __syncthreads();

    const int arow = tid >> 2;   // 0..63
    const int ach  = tid & 3;    // 0..3

    // ---- gather + convert into XQ (src+pos) and XV (src) chunk layouts ----
    {
        int v = sv[arow];
        const float* srow = src + (size_t)v * CDIM;
        const float* prow = pos + (size_t)v * CDIM;
        #pragma unroll
        for (int c = 0; c < 6; c++) {
            int col = c * 32 + ach * 8;
            float4 s0 = *(const float4*)(srow + col);
            float4 s1 = *(const float4*)(srow + col + 4);
            float4 p0 = *(const float4*)(prow + col);
            float4 p1 = *(const float4*)(prow + col + 4);
            uint4 fv, qv;
            fv.x = pack_bf16(s0.x, s0.y); fv.y = pack_bf16(s0.z, s0.w);
            fv.z = pack_bf16(s1.x, s1.y); fv.w = pack_bf16(s1.z, s1.w);
            qv.x = pack_bf16(s0.x + p0.x, s0.y + p0.y);
            qv.y = pack_bf16(s0.z + p0.z, s0.w + p0.w);
            qv.z = pack_bf16(s1.x + p1.x, s1.y + p1.y);
            qv.w = pack_bf16(s1.z + p1.z, s1.w + p1.w);
            *(uint4*)(smem + QK_XV + c * 5120 + arow * 80 + ach * 16) = fv;
            *(uint4*)(smem + QK_XQ + c * 5120 + arow * 80 + ach * 16) = qv;
        }
    }
    __syncthreads();

    const int a_row = wr * 32 + (lane & 7) + ((lane >> 3) & 1) * 8;
    const int a_cb  = ((lane >> 4) & 1) * 4;
    const int b_row = wc * 48 + (lane & 7) + ((lane >> 4) & 1) * 8;
    const int b_cb  = ((lane >> 3) & 1) * 4;

    #pragma unroll 1
    for (int g = 0; g < 3; g++) {
        const __nv_bfloat16* W = wqkv + (size_t)g * 192 * CDIM;
        const uint32_t xbase = sbase + (g == 2 ? QK_XV : QK_XQ);

        auto issueW = [&](int kc) {
            uint32_t sW = sbase + QK_WS + (kc % 3) * QK_WSTG;
            #pragma unroll
            for (int r = 0; r < 3; r++) {
                int rr = arow + r * 64;
                cp16(sW + rr * 80 + ach * 16, W + (size_t)rr * CDIM + kc * 32 + ach * 8);
            }
            CP_COMMIT();
        };
        issueW(0); issueW(1);

        float acc[2][6][4];
        #pragma unroll
        for (int m = 0; m < 2; m++)
            #pragma unroll
            for (int n = 0; n < 6; n++)
                #pragma unroll
                for (int i = 0; i < 4; i++) acc[m][n][i] = 0.f;

        for (int kc = 0; kc < 6; kc++) {
            CP_WAIT1();
            __syncthreads();
            if (kc + 2 < 6) issueW(kc + 2);
            else CP_COMMIT();

            const uint32_t stA = xbase + kc * 5120;
            const uint32_t stB = sbase + QK_WS + (kc % 3) * QK_WSTG;
            #pragma unroll
            for (int k16 = 0; k16 < 2; k16++) {
                const int kp = k16 * 8;
                uint32_t ah[4], ah2[4];
                ldsm_x4(ah[0], ah[1], ah[2], ah[3],
                        stA + (uint32_t)((a_row * 20 + kp + a_cb) * 4));
                ldsm_x4(ah2[0], ah2[1], ah2[2], ah2[3],
                        stA + (uint32_t)(((a_row + 16) * 20 + kp + a_cb) * 4));
                uint32_t bh[12];
                #pragma unroll
                for (int p = 0; p < 3; p++) {
                    ldsm_x4(bh[p * 4 + 0], bh[p * 4 + 1], bh[p * 4 + 2], bh[p * 4 + 3],
                            stB + (uint32_t)(((b_row + p * 16) * 20 + kp + b_cb) * 4));
                }
                #pragma unroll
                for (int nt = 0; nt < 6; nt++) {
                    uint32_t bh0 = bh[nt * 2], bh1 = bh[nt * 2 + 1];
                    mma_bf16(acc[0][nt], ah[0],  ah[1],  ah[2],  ah[3],  bh0, bh1);
                    mma_bf16(acc[1][nt], ah2[0], ah2[1], ah2[2], ah2[3], bh0, bh1);
                }
            }
            __syncthreads();
        }

        // ---- epilogue: bias + bf16 store ----
        const float* bias = bqkv + g * 192;
        __nv_bfloat16* C = (g < 2) ? g_qk : g_v;
        const int ldC  = (g < 2) ? 2 * CDIM : CDIM;
        const int coff = (g == 1) ? CDIM : 0;
        #pragma unroll
        for (int mt = 0; mt < 2; mt++) {
            int r0 = row0 + wr * 32 + mt * 16 + (lane >> 2);
            #pragma unroll
            for (int nt = 0; nt < 6; nt++) {
                int c = wc * 48 + nt * 8 + 2 * (lane & 3);
                float bx = bias[c], by = bias[c + 1];
                float o0x = acc[mt][nt][0] + bx, o0y = acc[mt][nt][1] + by;
                float o1x = acc[mt][nt][2] + bx, o1y = acc[mt][nt][3] + by;
                *(uint32_t*)&C[(size_t)r0 * ldC + coff + c]       = pack_bf16(o0x, o0y);
                *(uint32_t*)&C[(size_t)(r0 + 8) * ldC + coff + c] = pack_bf16(o1x, o1y);
            }
        }
    }
}

// ---------------- bf16 GEMM, BM=64 BN=192 BK=32, cp.async 3-stage ----------
#define STAGE_B 20480
#define OFF_B_ST 5120
#define OFF_SV_B (3 * STAGE_B)
#define GEMM_SMEM_BYTES (OFF_SV_B + 256)

template <int RELU, int EPI>
__global__ void __launch_bounds__(256, 2)
gemm_bf16(const __nv_bfloat16* __restrict__ A, const __nv_bfloat16* __restrict__ B,
          const float* __restrict__ bias,
          void* __restrict__ Cv, void* __restrict__ C2v,
          const int* __restrict__ vidx,
          const float* __restrict__ e_src, const float* __restrict__ e_x,
          const float* __restrict__ e_g1, const float* __restrict__ e_b1,
          const float* __restrict__ e_g2, const float* __restrict__ e_b2,
          int N, int K)
{
    extern __shared__ char smem[];
    const uint32_t sbase = (uint32_t)__cvta_generic_to_shared(smem);
    int* sv = (int*)(smem + OFF_SV_B);

    const int tid  = threadIdx.x;
    const int lane = tid & 31;
    const int warp = tid >> 5;
    const int wr   = warp >> 2;
    const int wc   = warp & 3;
    const int row0 = blockIdx.x * 64;
    const int col0 = blockIdx.y * 192;

    if (EPI == 1 && tid < 64) sv[tid] = vidx[row0 + tid];

    float acc[2][6][4];
    #pragma unroll
    for (int m = 0; m < 2; m++)
        #pragma unroll
        for (int n = 0; n < 6; n++)
            #pragma unroll
            for (int i = 0; i < 4; i++) acc[m][n][i] = 0.f;

    const __nv_bfloat16* Arow = A + (size_t)row0 * K;
    const __nv_bfloat16* Brow = B + (size_t)col0 * K;
    const int arow = tid >> 2;
    const int ach  = tid & 3;

    auto issue = [&](int it) {
        int st = it % 3;
        uint32_t sA = sbase + st * STAGE_B;
        int kb = it * 32;
        cp16(sA + arow * 80 + ach * 16, Arow + (size_t)arow * K + kb + ach * 8);
        uint32_t sB = sA + OFF_B_ST;
        #pragma unroll
        for (int r = 0; r < 3; r++) {
            int rr = arow + r * 64;
            cp16(sB + rr * 80 + ach * 16, Brow + (size_t)rr * K + kb + ach * 8);
        }
        CP_COMMIT();
    };

    const int a_row = wr * 32 + (lane & 7) + ((lane >> 3) & 1) * 8;
    const int a_cb  = ((lane >> 4) & 1) * 4;
    const int b_row = wc * 48 + (lane & 7) + ((lane >> 4) & 1) * 8;
    const int b_cb  = ((lane >> 3) & 1) * 4;

    const int nk = K >> 5;
    issue(0); issue(1);

    for (int it = 0; it < nk; it++) {
        CP_WAIT1();
        __syncthreads();
        if (it + 2 < nk) issue(it + 2);
        else CP_COMMIT();

        const int st = it % 3;
        const uint32_t stA = sbase + st * STAGE_B;
        const uint32_t stB = stA + OFF_B_ST;
        #pragma unroll
        for (int k16 = 0; k16 < 2; k16++) {
            const int kp = k16 * 8;
            uint32_t ah[4], ah2[4];
            ldsm_x4(ah[0], ah[1], ah[2], ah[3],
                    stA + (uint32_t)((a_row * 20 + kp + a_cb) * 4));
            ldsm_x4(ah2[0], ah2[1], ah2[2], ah2[3],
                    stA + (uint32_t)(((a_row + 16) * 20 + kp + a_cb) * 4));
            uint32_t bh[12];
            #pragma unroll
            for (int p = 0; p < 3; p++) {
                ldsm_x4(bh[p * 4 + 0], bh[p * 4 + 1], bh[p * 4 + 2], bh[p * 4 + 3],
                        stB + (uint32_t)(((b_row + p * 16) * 20 + kp + b_cb) * 4));
            }
            #pragma unroll
            for (int nt = 0; nt < 6; nt++) {
                uint32_t bh0 = bh[nt * 2], bh1 = bh[nt * 2 + 1];
                mma_bf16(acc[0][nt], ah[0],  ah[1],  ah[2],  ah[3],  bh0, bh1);
                mma_bf16(acc[1][nt], ah2[0], ah2[1], ah2[2], ah2[3], bh0, bh1);
            }
        }
        __syncthreads();
    }

    // ================= epilogue =================
    if (EPI == 0) {
        __nv_bfloat16* Cb = (__nv_bfloat16*)Cv;
        #pragma unroll
        for (int mt = 0; mt < 2; mt++) {
            int r0 = row0 + wr * 32 + mt * 16 + (lane >> 2);
            #pragma unroll
            for (int nt = 0; nt < 6; nt++) {
                int c = col0 + wc * 48 + nt * 8 + 2 * (lane & 3);
                float bx = bias[c], by = bias[c + 1];
                float o0x = acc[mt][nt][0] + bx, o0y = acc[mt][nt][1] + by;
                float o1x = acc[mt][nt][2] + bx, o1y = acc[mt][nt][3] + by;
                if (RELU) {
                    o0x = fmaxf(o0x, 0.f); o0y = fmaxf(o0y, 0.f);
                    o1x = fmaxf(o1x, 0.f); o1y = fmaxf(o1y, 0.f);
                }
                *(uint32_t*)&Cb[(size_t)r0 * N + c]       = pack_bf16(o0x, o0y);
                *(uint32_t*)&Cb[(size_t)(r0 + 8) * N + c] = pack_bf16(o1x, o1y);
            }
        }
        return;
    }

    float* rsum = (float*)smem;
    float* rsq  = (float*)smem + 64;
    if (tid < 64) { rsum[tid] = 0.f; rsq[tid] = 0.f; }
    __syncthreads();

    #pragma unroll
    for (int mt = 0; mt < 2; mt++) {
        #pragma unroll
        for (int half = 0; half < 2; half++) {
            int row = wr * 32 + mt * 16 + (lane >> 2) + half * 8;
            float s1 = 0.f, s2 = 0.f;
            #pragma unroll
            for (int nt = 0; nt < 6; nt++) {
                int c = wc * 48 + nt * 8 + 2 * (lane & 3);
                float2 res;
                if (EPI == 1) {
                    int v = sv[row];
                    res = *(const float2*)&e_src[(size_t)v * CDIM + c];
                } else {
                    res = *(const float2*)&e_x[(size_t)(row0 + row) * CDIM + c];
                }
                float v0 = acc[mt][nt][half * 2 + 0] + bias[c]     + res.x;
                float v1 = acc[mt][nt][half * 2 + 1] + bias[c + 1] + res.y;
                acc[mt][nt][half * 2 + 0] = v0;
                acc[mt][nt][half * 2 + 1] = v1;
                s1 += v0 + v1; s2 += v0 * v0 + v1 * v1;
            }
            atomicAdd(&rsum[row], s1);
            atomicAdd(&rsq[row],  s2);
        }
    }
    __syncthreads();

    if (EPI == 1) {
        float* Cf = (float*)Cv;
        __nv_bfloat16* Cb2 = (__nv_bfloat16*)C2v;
        #pragma unroll
        for (int mt = 0; mt < 2; mt++) {
            #pragma unroll
            for (int half = 0; half < 2; half++) {
                int row = wr * 32 + mt * 16 + (lane >> 2) + half * 8;
                int v = sv[row];
                float mean = rsum[row] * (1.f / CDIM);
                float var  = rsq[row] * (1.f / CDIM) - mean * mean;
                float inv  = rsqrtf(var + 1e-5f);
                #pragma unroll
                for (int nt = 0; nt < 6; nt++) {
                    int c = wc * 48 + nt * 8 + 2 * (lane & 3);
                    float ox = (acc[mt][nt][half * 2 + 0] - mean) * inv * e_g1[c]     + e_b1[c];
                    float oy = (acc[mt][nt][half * 2 + 1] - mean) * inv * e_g1[c + 1] + e_b1[c + 1];
                    float2 o; o.x = ox; o.y = oy;
                    *(float2*)&Cf[(size_t)v * CDIM + c] = o;
                    *(uint32_t*)&Cb2[(size_t)v * CDIM + c] = pack_bf16(ox, oy);
                }
            }
        }
        return;
    }

    // EPI == 2: LN2 then +src then LN3 -> fp32
    float su1[4], su2[4];
    #pragma unroll
    for (int mt = 0; mt < 2; mt++) {
        #pragma unroll
        for (int half = 0; half < 2; half++) {
            int row = wr * 32 + mt * 16 + (lane >> 2) + half * 8;
            float mean = rsum[row] * (1.f / CDIM);
            float var  = rsq[row] * (1.f / CDIM) - mean * mean;
            float inv  = rsqrtf(var + 1e-5f);
            float s1 = 0.f, s2 = 0.f;
            #pragma unroll
            for (int nt = 0; nt < 6; nt++) {
                int c = wc * 48 + nt * 8 + 2 * (lane & 3);
                float2 sr = *(const float2*)&e_src[(size_t)(row0 + row) * CDIM + c];
                float u0 = (acc[mt][nt][half * 2 + 0] - mean) * inv * e_g1[c]     + e_b1[c]     + sr.x;
                float u1 = (acc[mt][nt][half * 2 + 1] - mean) * inv * e_g1[c + 1] + e_b1[c + 1] + sr.y;
                acc[mt][nt][half * 2 + 0] = u0;
                acc[mt][nt][half * 2 + 1] = u1;
                s1 += u0 + u1; s2 += u0 * u0 + u1 * u1;
            }
            su1[mt * 2 + half] = s1;
            su2[mt * 2 + half] = s2;
        }
    }
    __syncthreads();
    if (tid < 64) { rsum[tid] = 0.f; rsq[tid] = 0.f; }
    __syncthreads();
    #pragma unroll
    for (int mt = 0; mt < 2; mt++) {
        #pragma unroll
        for (int half = 0; half < 2; half++) {
            int row = wr * 32 + mt * 16 + (lane >> 2) + half * 8;
            atomicAdd(&rsum[row], su1[mt * 2 + half]);
            atomicAdd(&rsq[row],  su2[mt * 2 + half]);
        }
    }
    __syncthreads();
    {
        float* Cf = (float*)Cv;
        #pragma unroll
        for (int mt = 0; mt < 2; mt++) {
            #pragma unroll
            for (int half = 0; half < 2; half++) {
                int row = wr * 32 + mt * 16 + (lane >> 2) + half * 8;
                float mean = rsum[row] * (1.f / CDIM);
                float var  = rsq[row] * (1.f / CDIM) - mean * mean;
                float inv  = rsqrtf(var + 1e-5f);
                #pragma unroll
                for (int nt = 0; nt < 6; nt++) {
                    int c = wc * 48 + nt * 8 + 2 * (lane & 3);
                    float2 o;
                    o.x = (acc[mt][nt][half * 2 + 0] - mean) * inv * e_g2[c]     + e_b2[c];
                    o.y = (acc[mt][nt][half * 2 + 1] - mean) * inv * e_g2[c + 1] + e_b2[c + 1];
                    *(float2*)&Cf[(size_t)(row0 + row) * CDIM + c] = o;
                }
            }
        }
    }
}

// ---------------- attention (tensor-core): 192 thr = 2 pairs x 3 warps ------
__global__ void __launch_bounds__(192)
attn_kernel(const uint8_t* __restrict__ mask)
{
    __shared__ __nv_bfloat16 qs[2][SETSZ][40];
    __shared__ __nv_bfloat16 ks[2][SETSZ][40];
    __shared__ __nv_bfloat16 vs[2][SETSZ][40];
    __shared__ float mf[2][SETSZ];

    const int tid  = threadIdx.x;
    const int lane = tid & 31;
    const int warp = tid >> 5;
    const int p    = warp / 3;
    const int w    = warp % 3;

    {
        int lt = tid % 96;
        int pp = tid / 96;
        int gpp = blockIdx.x * 2 + pp;
        int ss = gpp >> 3, hh = gpp & 7;
        for (int task = lt; task < SETSZ * 3; task += 96) {
            int row = task / 3, ch = task % 3;
            size_t ro = (size_t)ss * SETSZ + row;
            const __nv_bfloat16* qrow = g_qk + ro * (2 * CDIM) + (size_t)hh * HD + ch * 8;
            *(uint4*)&qs[pp][row][ch * 8] = *(const uint4*)qrow;
            *(uint4*)&ks[pp][row][ch * 8] = *(const uint4*)(qrow + CDIM);
            *(uint4*)&vs[pp][row][ch * 8] = *(const uint4*)(g_v + ro * CDIM + (size_t)hh * HD + ch * 8);
        }
        for (int row = lt; row < SETSZ; row += 96) {
            *(uint4*)&qs[pp][row][24] = make_uint4(0, 0, 0, 0);
            *(uint4*)&ks[pp][row][24] = make_uint4(0, 0, 0, 0);
            *(uint4*)&vs[pp][row][24] = make_uint4(0, 0, 0, 0);
            mf[pp][row] = (mask[(size_t)ss * SETSZ + row] != 0) ? -1e9f : 0.f;
        }
    }
    __syncthreads();

    const int gp = blockIdx.x * 2 + p;
    const int s  = gp >> 3;
    const int h  = gp & 7;

    const uint32_t sq = (uint32_t)__cvta_generic_to_shared(&qs[p][0][0]);
    const uint32_t sk = (uint32_t)__cvta_generic_to_shared(&ks[p][0][0]);
    const uint32_t svv = (uint32_t)__cvta_generic_to_shared(&vs[p][0][0]);

    const int a_row = w * 16 + (lane & 7) + ((lane >> 3) & 1) * 8;
    const int a_cb  = ((lane >> 4) & 1) * 4;
    const int b_row = (lane & 7) + ((lane >> 4) & 1) * 8;
    const int b_cb  = ((lane >> 3) & 1) * 4;

    float sacc[6][4];
    #pragma unroll
    for (int nt = 0; nt < 6; nt++)
        #pragma unroll
        for (int i = 0; i < 4; i++) sacc[nt][i] = 0.f;

    #pragma unroll
    for (int kt = 0; kt < 2; kt++) {
        uint32_t qa[4];
        ldsm_x4(qa[0], qa[1], qa[2], qa[3],
                sq + (uint32_t)((a_row * 20 + kt * 8 + a_cb) * 4));
        uint32_t kb[12];
        #pragma unroll
        for (int t = 0; t < 3; t++)
            ldsm_x4(kb[t * 4 + 0], kb[t * 4 + 1], kb[t * 4 + 2], kb[t * 4 + 3],
                    sk + (uint32_t)(((b_row + t * 16) * 20 + kt * 8 + b_cb) * 4));
        #pragma unroll
        for (int nt = 0; nt < 6; nt++)
            mma_bf16(sacc[nt], qa[0], qa[1], qa[2], qa[3], kb[nt * 2], kb[nt * 2 + 1]);
    }

    const float scale = 0.20412414523193154f;
    float m0 = -1e30f, m1 = -1e30f;
    #pragma unroll
    for (int nt = 0; nt < 6; nt++) {
        int j0 = nt * 8 + (lane & 3) * 2;
        float mv0 = mf[p][j0], mv1 = mf[p][j0 + 1];
        sacc[nt][0] = sacc[nt][0] * scale + mv0;
        sacc[nt][1] = sacc[nt][1] * scale + mv1;
        sacc[nt][2] = sacc[nt][2] * scale + mv0;
        sacc[nt][3] = sacc[nt][3] * scale + mv1;
        m0 = fmaxf(m0, fmaxf(sacc[nt][0], sacc[nt][1]));
        m1 = fmaxf(m1, fmaxf(sacc[nt][2], sacc[nt][3]));
    }
    m0 = fmaxf(m0, __shfl_xor_sync(0xFFFFFFFFu, m0, 1));
    m0 = fmaxf(m0, __shfl_xor_sync(0xFFFFFFFFu, m0, 2));
    m1 = fmaxf(m1, __shfl_xor_sync(0xFFFFFFFFu, m1, 1));
    m1 = fmaxf(m1, __shfl_xor_sync(0xFFFFFFFFu, m1, 2));
    float s0 = 0.f, s1 = 0.f;
    #pragma unroll
    for (int nt = 0; nt < 6; nt++) {
        sacc[nt][0] = __expf(sacc[nt][0] - m0);
        sacc[nt][1] = __expf(sacc[nt][1] - m0);
        sacc[nt][2] = __expf(sacc[nt][2] - m1);
        sacc[nt][3] = __expf(sacc[nt][3] - m1);
        s0 += sacc[nt][0] + sacc[nt][1];
        s1 += sacc[nt][2] + sacc[nt][3];
    }
    s0 += __shfl_xor_sync(0xFFFFFFFFu, s0, 1);
    s0 += __shfl_xor_sync(0xFFFFFFFFu, s0, 2);
    s1 += __shfl_xor_sync(0xFFFFFFFFu, s1, 1);
    s1 += __shfl_xor_sync(0xFFFFFFFFu, s1, 2);
    float i0 = 1.f / s0, i1 = 1.f / s1;
    #pragma unroll
    for (int nt = 0; nt < 6; nt++) {
        sacc[nt][0] *= i0; sacc[nt][1] *= i0;
        sacc[nt][2] *= i1; sacc[nt][3] *= i1;
    }

    uint32_t pah[3][4], pal[3][4];
    #pragma unroll
    for (int kt = 0; kt < 3; kt++) {
        const float* t0 = sacc[2 * kt];
        const float* t1 = sacc[2 * kt + 1];
        float src4[4][2] = {{t0[0], t0[1]}, {t0[2], t0[3]}, {t1[0], t1[1]}, {t1[2], t1[3]}};
        #pragma unroll
        for (int r = 0; r < 4; r++) {
            __nv_bfloat162 hh = __floats2bfloat162_rn(src4[r][0], src4[r][1]);
            pah[kt][r] = *reinterpret_cast<const uint32_t*>(&hh);
            float lx = src4[r][0] - __bfloat162float(hh.x);
            float ly = src4[r][1] - __bfloat162float(hh.y);
            pal[kt][r] = pack_bf16(lx, ly);
        }
    }

    float oacc[3][4];
    #pragma unroll
    for (int d = 0; d < 3; d++)
        #pragma unroll
        for (int i = 0; i < 4; i++) oacc[d][i] = 0.f;

    const int v_row = (lane & 7) + ((lane >> 3) & 1) * 8;
    const int v_cb  = ((lane >> 4) & 1) * 4;
    #pragma unroll
    for (int kt = 0; kt < 3; kt++) {
        uint32_t base = svv + (uint32_t)(((16 * kt + v_row) * 20 + v_cb) * 4);
        uint32_t b0[4], b1[4];
        ldsm_x4_t(b0[0], b0[1], b0[2], b0[3], base);
        ldsm_x4_t(b1[0], b1[1], b1[2], b1[3], base + 32);
        mma_bf16(oacc[0], pah[kt][0], pah[kt][1], pah[kt][2], pah[kt][3], b0[0], b0[1]);
        mma_bf16(oacc[0], pal[kt][0], pal[kt][1], pal[kt][2], pal[kt][3], b0[0], b0[1]);
        mma_bf16(oacc[1], pah[kt][0], pah[kt][1], pah[kt][2], pah[kt][3], b0[2], b0[3]);
        mma_bf16(oacc[1], pal[kt][0], pal[kt][1], pal[kt][2], pal[kt][3], b0[2], b0[3]);
        mma_bf16(oacc[2], pah[kt][0], pah[kt][1], pah[kt][2], pah[kt][3], b1[0], b1[1]);
        mma_bf16(oacc[2], pal[kt][0], pal[kt][1], pal[kt][2], pal[kt][3], b1[0], b1[1]);
    }

    {
        size_t r0 = (size_t)s * SETSZ + w * 16 + (lane >> 2);
        int dbase = h * HD + (lane & 3) * 2;
        #pragma unroll
        for (int db = 0; db < 3; db++) {
            int dd = dbase + db * 8;
            *(uint32_t*)&g_ctx[r0 * CDIM + dd]       = pack_bf16(oacc[db][0], oacc[db][1]);
            *(uint32_t*)&g_ctx[(r0 + 8) * CDIM + dd] = pack_bf16(oacc[db][2], oacc[db][3]);
        }
    }
}

// ---------------- launch --------------------------------------------------
extern "C" void kernel_launch(void* const* d_in, const int* in_sizes, int n_in,
                              void* d_out, int out_size)
{
    const float* src   = (const float*)d_in[0];
    const float* pos   = (const float*)d_in[1];
    const float* w_qkv = (const float*)d_in[2];
    const float* b_qkv = (const float*)d_in[3];
    const float* w_out = (const float*)d_in[4];
    const float* b_out = (const float*)d_in[5];
    const float* w1    = (const float*)d_in[6];
    const float* b1    = (const float*)d_in[7];
    const float* w2    = (const float*)d_in[8];
    const float* b2    = (const float*)d_in[9];
    const float* ln1g  = (const float*)d_in[10];
    const float* ln1b  = (const float*)d_in[11];
    const float* ln2g  = (const float*)d_in[12];
    const float* ln2b  = (const float*)d_in[13];
    const float* ln3g  = (const float*)d_in[14];
    const float* ln3b  = (const float*)d_in[15];
    const int*   vidx  = (const int*)d_in[16];
    const uint8_t* msk = (const uint8_t*)d_in[17];
    float* out = (float*)d_out;

    __nv_bfloat16 *p_qk, *p_v, *p_ctx, *p_xb, *p_h;
    __nv_bfloat16 *p_wqkv, *p_wout, *p_w1, *p_w2;
    float *p_x;
    cudaGetSymbolAddress((void**)&p_qk,   g_qk);
    cudaGetSymbolAddress((void**)&p_v,    g_v);
    cudaGetSymbolAddress((void**)&p_ctx,  g_ctx);
    cudaGetSymbolAddress((void**)&p_x,    g_x);
    cudaGetSymbolAddress((void**)&p_xb,   g_xb);
    cudaGetSymbolAddress((void**)&p_h,    g_h);
    cudaGetSymbolAddress((void**)&p_wqkv, g_wqkv);
    cudaGetSymbolAddress((void**)&p_wout, g_wout);
    cudaGetSymbolAddress((void**)&p_w1,   g_w1);
    cudaGetSymbolAddress((void**)&p_w2,   g_w2);

    cudaFuncSetAttribute(qkv_fused, cudaFuncAttributeMaxDynamicSharedMemorySize, QK_SMEM);
    cudaFuncSetAttribute(gemm_bf16<0,1>, cudaFuncAttributeMaxDynamicSharedMemorySize, GEMM_SMEM_BYTES);
    cudaFuncSetAttribute(gemm_bf16<1,0>, cudaFuncAttributeMaxDynamicSharedMemorySize, GEMM_SMEM_BYTES);
    cudaFuncSetAttribute(gemm_bf16<0,2>, cudaFuncAttributeMaxDynamicSharedMemorySize, GEMM_SMEM_BYTES);

    // 0) weights -> bf16
    cvt_kernel<<<(3*CDIM*CDIM/2 + 255)/256, 256>>>(w_qkv, p_wqkv, 3*CDIM*CDIM/2);
    cvt_kernel<<<(CDIM*CDIM/2   + 255)/256, 256>>>(w_out, p_wout, CDIM*CDIM/2);
    cvt_kernel<<<(DFF*CDIM/2    + 255)/256, 256>>>(w1,    p_w1,   DFF*CDIM/2);
    cvt_kernel<<<(CDIM*DFF/2    + 255)/256, 256>>>(w2,    p_w2,   CDIM*DFF/2);

    const int MB = NVOX / 64;  // 3072

    // 1) fused gather + q,k,v projections
    qkv_fused<<<MB, 256, QK_SMEM>>>(src, pos, vidx, p_wqkv, b_qkv);

    // 2) attention (tensor cores)
    attn_kernel<<<(SETS * NHEAD) / 2, 192>>>(msk);

    // 3) out-proj + scatter + residual + LN1 -> g_x (fp32) + g_xb (bf16)
    gemm_bf16<0,1><<<dim3(MB, 1), 256, GEMM_SMEM_BYTES>>>(
        p_ctx, p_wout, b_out, p_x, p_xb, vidx,
        src, nullptr, ln1g, ln1b, nullptr, nullptr,
        CDIM, CDIM);

    // 4) FFN1 (relu) -> g_h bf16
    gemm_bf16<1,0><<<dim3(MB, 2), 256, GEMM_SMEM_BYTES>>>(
        p_xb, p_w1, b1, p_h, nullptr, nullptr,
        nullptr, nullptr, nullptr, nullptr, nullptr, nullptr,
        DFF, CDIM);

    // 5) FFN2 + LN2 + residual + LN3 -> out (fp32)
    gemm_bf16<0,2><<<dim3(MB, 1), 256, GEMM_SMEM_BYTES>>>(
        p_h, p_w2, b2, out, nullptr, nullptr,
        src, p_x, ln2g, ln2b, ln3g, ln3b,
        CDIM, DFF);
}

// round 15
// speedup vs baseline: 1.1583x; 1.0626x over previous
#include <cuda_runtime.h>
#include <cuda_bf16.h>
#include <cstdint>
#include <cstddef>

// ---------------- problem constants ----------------
#define NVOX   196608
#define CDIM   192
#define SETS   4096
#define SETSZ  48
#define NHEAD  8
#define HD     24
#define DFF    384

// ---------------- scratch (device globals) ----------------
__device__ __nv_bfloat16 g_qk [(size_t)NVOX * 2 * CDIM]; // q cols 0..191, k 192..383
__device__ __nv_bfloat16 g_v  [(size_t)NVOX * CDIM];
__device__ __nv_bfloat16 g_ctx[(size_t)NVOX * CDIM];
__device__ float         g_x  [(size_t)NVOX * CDIM];     // LN1 out, fp32
__device__ __nv_bfloat16 g_xb [(size_t)NVOX * CDIM];     // LN1 out, bf16
__device__ __nv_bfloat16 g_h  [(size_t)NVOX * DFF];
// bf16 weights
__device__ __nv_bfloat16 g_wqkv[3 * CDIM * CDIM];
__device__ __nv_bfloat16 g_wout[CDIM * CDIM];
__device__ __nv_bfloat16 g_w1  [DFF * CDIM];
__device__ __nv_bfloat16 g_w2  [CDIM * DFF];

// ---------------- helpers ----------------
__device__ __forceinline__ uint32_t pack_bf16(float x, float y)
{
    __nv_bfloat162 h2 = __floats2bfloat162_rn(x, y);
    return *reinterpret_cast<const uint32_t*>(&h2);
}

__device__ __forceinline__ void mma_bf16(float c[4],
    uint32_t a0, uint32_t a1, uint32_t a2, uint32_t a3,
    uint32_t b0, uint32_t b1)
{
    asm volatile(
        "mma.sync.aligned.m16n8k16.row.col.f32.bf16.bf16.f32 "
        "{%0,%1,%2,%3}, {%4,%5,%6,%7}, {%8,%9}, {%0,%1,%2,%3};\n"
        : "+f"(c[0]), "+f"(c[1]), "+f"(c[2]), "+f"(c[3])
        : "r"(a0), "r"(a1), "r"(a2), "r"(a3), "r"(b0), "r"(b1));
}
__device__ __forceinline__ void ldsm_x4(uint32_t& r0, uint32_t& r1,
                                        uint32_t& r2, uint32_t& r3, uint32_t addr)
{
    asm volatile("ldmatrix.sync.aligned.m8n8.x4.shared.b16 {%0,%1,%2,%3}, [%4];"
                 : "=r"(r0), "=r"(r1), "=r"(r2), "=r"(r3) : "r"(addr));
}
__device__ __forceinline__ void ldsm_x4_t(uint32_t& r0, uint32_t& r1,
                                          uint32_t& r2, uint32_t& r3, uint32_t addr)
{
    asm volatile("ldmatrix.sync.aligned.m8n8.x4.trans.shared.b16 {%0,%1,%2,%3}, [%4];"
                 : "=r"(r0), "=r"(r1), "=r"(r2), "=r"(r3) : "r"(addr));
}
__device__ __forceinline__ void cp16(uint32_t saddr, const void* gaddr)
{
    asm volatile("cp.async.cg.shared.global [%0], [%1], 16;"
                 :: "r"(saddr), "l"(gaddr) : "memory");
}
#define CP_COMMIT() asm volatile("cp.async.commit_group;" ::: "memory")
#define CP_WAIT1()  asm volatile("cp.async.wait_group 1;" ::: "memory")
#define CP_WAIT0()  asm volatile("cp.async.wait_group 0;" ::: "memory")

// ---------------- all-weights fp32 -> bf16 conversion (one launch) ---------
#define CVT_N0 (3 * CDIM * CDIM / 2)   // 55296
#define CVT_N1 (CDIM * CDIM / 2)       // 18432
#define CVT_N2 (DFF * CDIM / 2)        // 36864
#define CVT_N3 (CDIM * DFF / 2)        // 36864
__global__ void cvt_all(const float* __restrict__ a, const float* __restrict__ b,
                        const float* __restrict__ c, const float* __restrict__ d)
{
    int i = blockIdx.x * blockDim.x + threadIdx.x;
    if (i < CVT_N0) {
        ((uint32_t*)g_wqkv)[i] = pack_bf16(a[2 * i], a[2 * i + 1]);
    } else if (i < CVT_N0 + CVT_N1) {
        int j = i - CVT_N0;
        ((uint32_t*)g_wout)[j] = pack_bf16(b[2 * j], b[2 * j + 1]);
    } else if (i < CVT_N0 + CVT_N1 + CVT_N2) {
        int j = i - CVT_N0 - CVT_N1;
        ((uint32_t*)g_w1)[j] = pack_bf16(c[2 * j], c[2 * j + 1]);
    } else if (i < CVT_N0 + CVT_N1 + CVT_N2 + CVT_N3) {
        int j = i - CVT_N0 - CVT_N1 - CVT_N2;
        ((uint32_t*)g_w2)[j] = pack_bf16(d[2 * j], d[2 * j + 1]);
    }
}

// ---------------- fused gather + QKV projection (2 CTAs/SM) ----------------
// 64 set-slot rows/block; gather into XQ/XV smem chunks; 3 GEMM groups with
// 2-stage distance-1 weight double buffer.
#define QK_XQ 0
#define QK_XV 30720
#define QK_WS 61440
#define QK_WSTG 15360
#define QK_SV (QK_WS + 2 * QK_WSTG)     // 92160
#define QK_SMEM (QK_SV + 256)           // 92416

__global__ void __launch_bounds__(256, 2)
qkv_fused(const float* __restrict__ src, const float* __restrict__ pos,
          const int* __restrict__ vidx,
          const __nv_bfloat16* __restrict__ wqkv, const float* __restrict__ bqkv)
{
    extern __shared__ char smem[];
    const uint32_t sbase = (uint32_t)__cvta_generic_to_shared(smem);
    int* sv = (int*)(smem + QK_SV);

    const int tid  = threadIdx.x;
    const int lane = tid & 31;
    const int warp = tid >> 5;
    const int wr   = warp >> 2;
    const int wc   = warp & 3;
    const int row0 = blockIdx.x * 64;

    if (tid < 64) sv[tid] = vidx[row0 + tid];
    __syncthreads();

    const int arow = tid >> 2;   // 0..63
    const int ach  = tid & 3;    // 0..3

    // ---- gather + convert into XQ (src+pos) and XV (src) chunk layouts ----
    {
        int v = sv[arow];
        const float* srow = src + (size_t)v * CDIM;
        const float* prow = pos + (size_t)v * CDIM;
        #pragma unroll
        for (int c = 0; c < 6; c++) {
            int col = c * 32 + ach * 8;
            float4 s0 = *(const float4*)(srow + col);
            float4 s1 = *(const float4*)(srow + col + 4);
            float4 p0 = *(const float4*)(prow + col);
            float4 p1 = *(const float4*)(prow + col + 4);
            uint4 fv, qv;
            fv.x = pack_bf16(s0.x, s0.y); fv.y = pack_bf16(s0.z, s0.w);
            fv.z = pack_bf16(s1.x, s1.y); fv.w = pack_bf16(s1.z, s1.w);
            qv.x = pack_bf16(s0.x + p0.x, s0.y + p0.y);
            qv.y = pack_bf16(s0.z + p0.z, s0.w + p0.w);
            qv.z = pack_bf16(s1.x + p1.x, s1.y + p1.y);
            qv.w = pack_bf16(s1.z + p1.z, s1.w + p1.w);
            *(uint4*)(smem + QK_XV + c * 5120 + arow * 80 + ach * 16) = fv;
            *(uint4*)(smem + QK_XQ + c * 5120 + arow * 80 + ach * 16) = qv;
        }
    }
    __syncthreads();

    const int a_row = wr * 32 + (lane & 7) + ((lane >> 3) & 1) * 8;
    const int a_cb  = ((lane >> 4) & 1) * 4;
    const int b_row = wc * 48 + (lane & 7) + ((lane >> 4) & 1) * 8;
    const int b_cb  = ((lane >> 3) & 1) * 4;

    #pragma unroll 1
    for (int g = 0; g < 3; g++) {
        const __nv_bfloat16* W = wqkv + (size_t)g * 192 * CDIM;
        const uint32_t xbase = sbase + (g == 2 ? QK_XV : QK_XQ);

        auto issueW = [&](int kc) {
            uint32_t sW = sbase + QK_WS + (kc & 1) * QK_WSTG;
            #pragma unroll
            for (int r = 0; r < 3; r++) {
                int rr = arow + r * 64;
                cp16(sW + rr * 80 + ach * 16, W + (size_t)rr * CDIM + kc * 32 + ach * 8);
            }
            CP_COMMIT();
        };
        issueW(0);

        float acc[2][6][4];
        #pragma unroll
        for (int m = 0; m < 2; m++)
            #pragma unroll
            for (int n = 0; n < 6; n++)
                #pragma unroll
                for (int i = 0; i < 4; i++) acc[m][n][i] = 0.f;

        for (int kc = 0; kc < 6; kc++) {
            if (kc + 1 < 6) { issueW(kc + 1); CP_WAIT1(); }
            else            { CP_WAIT0(); }
            __syncthreads();

            const uint32_t stA = xbase + kc * 5120;
            const uint32_t stB = sbase + QK_WS + (kc & 1) * QK_WSTG;
            #pragma unroll
            for (int k16 = 0; k16 < 2; k16++) {
                const int kp = k16 * 8;
                uint32_t ah[4], ah2[4];
                ldsm_x4(ah[0], ah[1], ah[2], ah[3],
                        stA + (uint32_t)((a_row * 20 + kp + a_cb) * 4));
                ldsm_x4(ah2[0], ah2[1], ah2[2], ah2[3],
                        stA + (uint32_t)(((a_row + 16) * 20 + kp + a_cb) * 4));
                uint32_t bh[12];
                #pragma unroll
                for (int p = 0; p < 3; p++) {
                    ldsm_x4(bh[p * 4 + 0], bh[p * 4 + 1], bh[p * 4 + 2], bh[p * 4 + 3],
                            stB + (uint32_t)(((b_row + p * 16) * 20 + kp + b_cb) * 4));
                }
                #pragma unroll
                for (int nt = 0; nt < 6; nt++) {
                    uint32_t bh0 = bh[nt * 2], bh1 = bh[nt * 2 + 1];
                    mma_bf16(acc[0][nt], ah[0],  ah[1],  ah[2],  ah[3],  bh0, bh1);
                    mma_bf16(acc[1][nt], ah2[0], ah2[1], ah2[2], ah2[3], bh0, bh1);
                }
            }
            __syncthreads();   // protect stage reuse by next issueW
        }

        // ---- epilogue: bias + bf16 store ----
        const float* bias = bqkv + g * 192;
        __nv_bfloat16* C = (g < 2) ? g_qk : g_v;
        const int ldC  = (g < 2) ? 2 * CDIM : CDIM;
        const int coff = (g == 1) ? CDIM : 0;
        #pragma unroll
        for (int mt = 0; mt < 2; mt++) {
            int r0 = row0 + wr * 32 + mt * 16 + (lane >> 2);
            #pragma unroll
            for (int nt = 0; nt < 6; nt++) {
                int c = wc * 48 + nt * 8 + 2 * (lane & 3);
                float bx = bias[c], by = bias[c + 1];
                float o0x = acc[mt][nt][0] + bx, o0y = acc[mt][nt][1] + by;
                float o1x = acc[mt][nt][2] + bx, o1y = acc[mt][nt][3] + by;
                *(uint32_t*)&C[(size_t)r0 * ldC + coff + c]       = pack_bf16(o0x, o0y);
                *(uint32_t*)&C[(size_t)(r0 + 8) * ldC + coff + c] = pack_bf16(o1x, o1y);
            }
        }
    }
}

// ---------------- FFN1: h = relu(xb @ W1^T + b1), xb staged once -----------
#define F1_XS 0
#define F1_WS 30720
#define F1_WSTG 15360
#define F1_SMEM (F1_WS + 2 * F1_WSTG + 256)   // 61696

__global__ void __launch_bounds__(256, 2)
ffn1_fused(const __nv_bfloat16* __restrict__ xb,
           const __nv_bfloat16* __restrict__ w1, const float* __restrict__ b1)
{
    extern __shared__ char smem[];
    const uint32_t sbase = (uint32_t)__cvta_generic_to_shared(smem);
    const int tid  = threadIdx.x;
    const int lane = tid & 31;
    const int warp = tid >> 5;
    const int wr   = warp >> 2;
    const int wc   = warp & 3;
    const int row0 = blockIdx.x * 64;

    const int arow = tid >> 2;
    const int ach  = tid & 3;

    // stage xb block (bf16, direct copy into chunk layout)
    #pragma unroll
    for (int c = 0; c < 6; c++)
        cp16(sbase + F1_XS + c * 5120 + arow * 80 + ach * 16,
             xb + (size_t)(row0 + arow) * CDIM + c * 32 + ach * 8);
    CP_COMMIT();
    CP_WAIT0();
    __syncthreads();

    const int a_row = wr * 32 + (lane & 7) + ((lane >> 3) & 1) * 8;
    const int a_cb  = ((lane >> 4) & 1) * 4;
    const int b_row = wc * 48 + (lane & 7) + ((lane >> 4) & 1) * 8;
    const int b_cb  = ((lane >> 3) & 1) * 4;

    #pragma unroll 1
    for (int g = 0; g < 2; g++) {
        const __nv_bfloat16* W = w1 + (size_t)g * 192 * CDIM;
        auto issueW = [&](int kc) {
            uint32_t sW = sbase + F1_WS + (kc & 1) * F1_WSTG;
            #pragma unroll
            for (int r = 0; r < 3; r++) {
                int rr = arow + r * 64;
                cp16(sW + rr * 80 + ach * 16, W + (size_t)rr * CDIM + kc * 32 + ach * 8);
            }
            CP_COMMIT();
        };
        issueW(0);

        float acc[2][6][4];
        #pragma unroll
        for (int m = 0; m < 2; m++)
            #pragma unroll
            for (int n = 0; n < 6; n++)
                #pragma unroll
                for (int i = 0; i < 4; i++) acc[m][n][i] = 0.f;

        for (int kc = 0; kc < 6; kc++) {
            if (kc + 1 < 6) { issueW(kc + 1); CP_WAIT1(); }
            else            { CP_WAIT0(); }
            __syncthreads();

            const uint32_t stA = sbase + F1_XS + kc * 5120;
            const uint32_t stB = sbase + F1_WS + (kc & 1) * F1_WSTG;
            #pragma unroll
            for (int k16 = 0; k16 < 2; k16++) {
                const int kp = k16 * 8;
                uint32_t ah[4], ah2[4];
                ldsm_x4(ah[0], ah[1], ah[2], ah[3],
                        stA + (uint32_t)((a_row * 20 + kp + a_cb) * 4));
                ldsm_x4(ah2[0], ah2[1], ah2[2], ah2[3],
                        stA + (uint32_t)(((a_row + 16) * 20 + kp + a_cb) * 4));
                uint32_t bh[12];
                #pragma unroll
                for (int p = 0; p < 3; p++) {
                    ldsm_x4(bh[p * 4 + 0], bh[p * 4 + 1], bh[p * 4 + 2], bh[p * 4 + 3],
                            stB + (uint32_t)(((b_row + p * 16) * 20 + kp + b_cb) * 4));
                }
                #pragma unroll
                for (int nt = 0; nt < 6; nt++) {
                    uint32_t bh0 = bh[nt * 2], bh1 = bh[nt * 2 + 1];
                    mma_bf16(acc[0][nt], ah[0],  ah[1],  ah[2],  ah[3],  bh0, bh1);
                    mma_bf16(acc[1][nt], ah2[0], ah2[1], ah2[2], ah2[3], bh0, bh1);
                }
            }
            __syncthreads();
        }

        // epilogue: bias + relu -> g_h bf16 (columns g*192..)
        const float* bias = b1 + g * 192;
        #pragma unroll
        for (int mt = 0; mt < 2; mt++) {
            int r0 = row0 + wr * 32 + mt * 16 + (lane >> 2);
            #pragma unroll
            for (int nt = 0; nt < 6; nt++) {
                int c = wc * 48 + nt * 8 + 2 * (lane & 3);
                float bx = bias[c], by = bias[c + 1];
                float o0x = fmaxf(acc[mt][nt][0] + bx, 0.f);
                float o0y = fmaxf(acc[mt][nt][1] + by, 0.f);
                float o1x = fmaxf(acc[mt][nt][2] + bx, 0.f);
                float o1y = fmaxf(acc[mt][nt][3] + by, 0.f);
                *(uint32_t*)&g_h[(size_t)r0 * DFF + g * 192 + c]       = pack_bf16(o0x, o0y);
                *(uint32_t*)&g_h[(size_t)(r0 + 8) * DFF + g * 192 + c] = pack_bf16(o1x, o1y);
            }
        }
    }
}

// ---------------- bf16 GEMM, BM=64 BN=192 BK=32, cp.async 3-stage ----------
#define STAGE_B 20480
#define OFF_B_ST 5120
#define OFF_SV_B (3 * STAGE_B)
#define GEMM_SMEM_BYTES (OFF_SV_B + 256)

template <int RELU, int EPI>
__global__ void __launch_bounds__(256, 2)
gemm_bf16(const __nv_bfloat16* __restrict__ A, const __nv_bfloat16* __restrict__ B,
          const float* __restrict__ bias,
          void* __restrict__ Cv, void* __restrict__ C2v,
          const int* __restrict__ vidx,
          const float* __restrict__ e_src, const float* __restrict__ e_x,
          const float* __restrict__ e_g1, const float* __restrict__ e_b1,
          const float* __restrict__ e_g2, const float* __restrict__ e_b2,
          int N, int K)
{
    extern __shared__ char smem[];
    const uint32_t sbase = (uint32_t)__cvta_generic_to_shared(smem);
    int* sv = (int*)(smem + OFF_SV_B);

    const int tid  = threadIdx.x;
    const int lane = tid & 31;
    const int warp = tid >> 5;
    const int wr   = warp >> 2;
    const int wc   = warp & 3;
    const int row0 = blockIdx.x * 64;
    const int col0 = blockIdx.y * 192;

    if (EPI == 1 && tid < 64) sv[tid] = vidx[row0 + tid];

    float acc[2][6][4];
    #pragma unroll
    for (int m = 0; m < 2; m++)
        #pragma unroll
        for (int n = 0; n < 6; n++)
            #pragma unroll
            for (int i = 0; i < 4; i++) acc[m][n][i] = 0.f;

    const __nv_bfloat16* Arow = A + (size_t)row0 * K;
    const __nv_bfloat16* Brow = B + (size_t)col0 * K;
    const int arow = tid >> 2;
    const int ach  = tid & 3;

    auto issue = [&](int it) {
        int st = it % 3;
        uint32_t sA = sbase + st * STAGE_B;
        int kb = it * 32;
        cp16(sA + arow * 80 + ach * 16, Arow + (size_t)arow * K + kb + ach * 8);
        uint32_t sB = sA + OFF_B_ST;
        #pragma unroll
        for (int r = 0; r < 3; r++) {
            int rr = arow + r * 64;
            cp16(sB + rr * 80 + ach * 16, Brow + (size_t)rr * K + kb + ach * 8);
        }
        CP_COMMIT();
    };

    const int a_row = wr * 32 + (lane & 7) + ((lane >> 3) & 1) * 8;
    const int a_cb  = ((lane >> 4) & 1) * 4;
    const int b_row = wc * 48 + (lane & 7) + ((lane >> 4) & 1) * 8;
    const int b_cb  = ((lane >> 3) & 1) * 4;

    const int nk = K >> 5;
    issue(0); issue(1);

    for (int it = 0; it < nk; it++) {
        CP_WAIT1();
        __syncthreads();
        if (it + 2 < nk) issue(it + 2);
        else CP_COMMIT();

        const int st = it % 3;
        const uint32_t stA = sbase + st * STAGE_B;
        const uint32_t stB = stA + OFF_B_ST;
        #pragma unroll
        for (int k16 = 0; k16 < 2; k16++) {
            const int kp = k16 * 8;
            uint32_t ah[4], ah2[4];
            ldsm_x4(ah[0], ah[1], ah[2], ah[3],
                    stA + (uint32_t)((a_row * 20 + kp + a_cb) * 4));
            ldsm_x4(ah2[0], ah2[1], ah2[2], ah2[3],
                    stA + (uint32_t)(((a_row + 16) * 20 + kp + a_cb) * 4));
            uint32_t bh[12];
            #pragma unroll
            for (int p = 0; p < 3; p++) {
                ldsm_x4(bh[p * 4 + 0], bh[p * 4 + 1], bh[p * 4 + 2], bh[p * 4 + 3],
                        stB + (uint32_t)(((b_row + p * 16) * 20 + kp + b_cb) * 4));
            }
            #pragma unroll
            for (int nt = 0; nt < 6; nt++) {
                uint32_t bh0 = bh[nt * 2], bh1 = bh[nt * 2 + 1];
                mma_bf16(acc[0][nt], ah[0],  ah[1],  ah[2],  ah[3],  bh0, bh1);
                mma_bf16(acc[1][nt], ah2[0], ah2[1], ah2[2], ah2[3], bh0, bh1);
            }
        }
        __syncthreads();
    }

    // ================= epilogue =================
    if (EPI == 0) {
        __nv_bfloat16* Cb = (__nv_bfloat16*)Cv;
        #pragma unroll
        for (int mt = 0; mt < 2; mt++) {
            int r0 = row0 + wr * 32 + mt * 16 + (lane >> 2);
            #pragma unroll
            for (int nt = 0; nt < 6; nt++) {
                int c = col0 + wc * 48 + nt * 8 + 2 * (lane & 3);
                float bx = bias[c], by = bias[c + 1];
                float o0x = acc[mt][nt][0] + bx, o0y = acc[mt][nt][1] + by;
                float o1x = acc[mt][nt][2] + bx, o1y = acc[mt][nt][3] + by;
                if (RELU) {
                    o0x = fmaxf(o0x, 0.f); o0y = fmaxf(o0y, 0.f);
                    o1x = fmaxf(o1x, 0.f); o1y = fmaxf(o1y, 0.f);
                }
                *(uint32_t*)&Cb[(size_t)r0 * N + c]       = pack_bf16(o0x, o0y);
                *(uint32_t*)&Cb[(size_t)(r0 + 8) * N + c] = pack_bf16(o1x, o1y);
            }
        }
        return;
    }

    float* rsum = (float*)smem;
    float* rsq  = (float*)smem + 64;
    if (tid < 64) { rsum[tid] = 0.f; rsq[tid] = 0.f; }
    __syncthreads();

    #pragma unroll
    for (int mt = 0; mt < 2; mt++) {
        #pragma unroll
        for (int half = 0; half < 2; half++) {
            int row = wr * 32 + mt * 16 + (lane >> 2) + half * 8;
            float s1 = 0.f, s2 = 0.f;
            #pragma unroll
            for (int nt = 0; nt < 6; nt++) {
                int c = wc * 48 + nt * 8 + 2 * (lane & 3);
                float2 res;
                if (EPI == 1) {
                    int v = sv[row];
                    res = *(const float2*)&e_src[(size_t)v * CDIM + c];
                } else {
                    res = *(const float2*)&e_x[(size_t)(row0 + row) * CDIM + c];
                }
                float v0 = acc[mt][nt][half * 2 + 0] + bias[c]     + res.x;
                float v1 = acc[mt][nt][half * 2 + 1] + bias[c + 1] + res.y;
                acc[mt][nt][half * 2 + 0] = v0;
                acc[mt][nt][half * 2 + 1] = v1;
                s1 += v0 + v1; s2 += v0 * v0 + v1 * v1;
            }
            atomicAdd(&rsum[row], s1);
            atomicAdd(&rsq[row],  s2);
        }
    }
    __syncthreads();

    if (EPI == 1) {
        float* Cf = (float*)Cv;
        __nv_bfloat16* Cb2 = (__nv_bfloat16*)C2v;
        #pragma unroll
        for (int mt = 0; mt < 2; mt++) {
            #pragma unroll
            for (int half = 0; half < 2; half++) {
                int row = wr * 32 + mt * 16 + (lane >> 2) + half * 8;
                int v = sv[row];
                float mean = rsum[row] * (1.f / CDIM);
                float var  = rsq[row] * (1.f / CDIM) - mean * mean;
                float inv  = rsqrtf(var + 1e-5f);
                #pragma unroll
                for (int nt = 0; nt < 6; nt++) {
                    int c = wc * 48 + nt * 8 + 2 * (lane & 3);
                    float ox = (acc[mt][nt][half * 2 + 0] - mean) * inv * e_g1[c]     + e_b1[c];
                    float oy = (acc[mt][nt][half * 2 + 1] - mean) * inv * e_g1[c + 1] + e_b1[c + 1];
                    float2 o; o.x = ox; o.y = oy;
                    *(float2*)&Cf[(size_t)v * CDIM + c] = o;
                    *(uint32_t*)&Cb2[(size_t)v * CDIM + c] = pack_bf16(ox, oy);
                }
            }
        }
        return;
    }

    // EPI == 2: LN2 then +src then LN3 -> fp32
    float su1[4], su2[4];
    #pragma unroll
    for (int mt = 0; mt < 2; mt++) {
        #pragma unroll
        for (int half = 0; half < 2; half++) {
            int row = wr * 32 + mt * 16 + (lane >> 2) + half * 8;
            float mean = rsum[row] * (1.f / CDIM);
            float var  = rsq[row] * (1.f / CDIM) - mean * mean;
            float inv  = rsqrtf(var + 1e-5f);
            float s1 = 0.f, s2 = 0.f;
            #pragma unroll
            for (int nt = 0; nt < 6; nt++) {
                int c = wc * 48 + nt * 8 + 2 * (lane & 3);
                float2 sr = *(const float2*)&e_src[(size_t)(row0 + row) * CDIM + c];
                float u0 = (acc[mt][nt][half * 2 + 0] - mean) * inv * e_g1[c]     + e_b1[c]     + sr.x;
                float u1 = (acc[mt][nt][half * 2 + 1] - mean) * inv * e_g1[c + 1] + e_b1[c + 1] + sr.y;
                acc[mt][nt][half * 2 + 0] = u0;
                acc[mt][nt][half * 2 + 1] = u1;
                s1 += u0 + u1; s2 += u0 * u0 + u1 * u1;
            }
            su1[mt * 2 + half] = s1;
            su2[mt * 2 + half] = s2;
        }
    }
    __syncthreads();
    if (tid < 64) { rsum[tid] = 0.f; rsq[tid] = 0.f; }
    __syncthreads();
    #pragma unroll
    for (int mt = 0; mt < 2; mt++) {
        #pragma unroll
        for (int half = 0; half < 2; half++) {
            int row = wr * 32 + mt * 16 + (lane >> 2) + half * 8;
            atomicAdd(&rsum[row], su1[mt * 2 + half]);
            atomicAdd(&rsq[row],  su2[mt * 2 + half]);
        }
    }
    __syncthreads();
    {
        float* Cf = (float*)Cv;
        #pragma unroll
        for (int mt = 0; mt < 2; mt++) {
            #pragma unroll
            for (int half = 0; half < 2; half++) {
                int row = wr * 32 + mt * 16 + (lane >> 2) + half * 8;
                float mean = rsum[row] * (1.f / CDIM);
                float var  = rsq[row] * (1.f / CDIM) - mean * mean;
                float inv  = rsqrtf(var + 1e-5f);
                #pragma unroll
                for (int nt = 0; nt < 6; nt++) {
                    int c = wc * 48 + nt * 8 + 2 * (lane & 3);
                    float2 o;
                    o.x = (acc[mt][nt][half * 2 + 0] - mean) * inv * e_g2[c]     + e_b2[c];
                    o.y = (acc[mt][nt][half * 2 + 1] - mean) * inv * e_g2[c + 1] + e_b2[c + 1];
                    *(float2*)&Cf[(size_t)(row0 + row) * CDIM + c] = o;
                }
            }
        }
    }
}

// ---------------- attention (tensor-core): 192 thr = 2 pairs x 3 warps ------
__global__ void __launch_bounds__(192)
attn_kernel(const uint8_t* __restrict__ mask)
{
    __shared__ __nv_bfloat16 qs[2][SETSZ][40];
    __shared__ __nv_bfloat16 ks[2][SETSZ][40];
    __shared__ __nv_bfloat16 vs[2][SETSZ][40];
    __shared__ float mf[2][SETSZ];

    const int tid  = threadIdx.x;
    const int lane = tid & 31;
    const int warp = tid >> 5;
    const int p    = warp / 3;
    const int w    = warp % 3;

    {
        int lt = tid % 96;
        int pp = tid / 96;
        int gpp = blockIdx.x * 2 + pp;
        int ss = gpp >> 3, hh = gpp & 7;
        for (int task = lt; task < SETSZ * 3; task += 96) {
            int row = task / 3, ch = task % 3;
            size_t ro = (size_t)ss * SETSZ + row;
            const __nv_bfloat16* qrow = g_qk + ro * (2 * CDIM) + (size_t)hh * HD + ch * 8;
            *(uint4*)&qs[pp][row][ch * 8] = *(const uint4*)qrow;
            *(uint4*)&ks[pp][row][ch * 8] = *(const uint4*)(qrow + CDIM);
            *(uint4*)&vs[pp][row][ch * 8] = *(const uint4*)(g_v + ro * CDIM + (size_t)hh * HD + ch * 8);
        }
        for (int row = lt; row < SETSZ; row += 96) {
            *(uint4*)&qs[pp][row][24] = make_uint4(0, 0, 0, 0);
            *(uint4*)&ks[pp][row][24] = make_uint4(0, 0, 0, 0);
            *(uint4*)&vs[pp][row][24] = make_uint4(0, 0, 0, 0);
            mf[pp][row] = (mask[(size_t)ss * SETSZ + row] != 0) ? -1e9f : 0.f;
        }
    }
    __syncthreads();

    const int gp = blockIdx.x * 2 + p;
    const int s  = gp >> 3;
    const int h  = gp & 7;

    const uint32_t sq = (uint32_t)__cvta_generic_to_shared(&qs[p][0][0]);
    const uint32_t sk = (uint32_t)__cvta_generic_to_shared(&ks[p][0][0]);
    const uint32_t svv = (uint32_t)__cvta_generic_to_shared(&vs[p][0][0]);

    const int a_row = w * 16 + (lane & 7) + ((lane >> 3) & 1) * 8;
    const int a_cb  = ((lane >> 4) & 1) * 4;
    const int b_row = (lane & 7) + ((lane >> 4) & 1) * 8;
    const int b_cb  = ((lane >> 3) & 1) * 4;

    float sacc[6][4];
    #pragma unroll
    for (int nt = 0; nt < 6; nt++)
        #pragma unroll
        for (int i = 0; i < 4; i++) sacc[nt][i] = 0.f;

    #pragma unroll
    for (int kt = 0; kt < 2; kt++) {
        uint32_t qa[4];
        ldsm_x4(qa[0], qa[1], qa[2], qa[3],
                sq + (uint32_t)((a_row * 20 + kt * 8 + a_cb) * 4));
        uint32_t kb[12];
        #pragma unroll
        for (int t = 0; t < 3; t++)
            ldsm_x4(kb[t * 4 + 0], kb[t * 4 + 1], kb[t * 4 + 2], kb[t * 4 + 3],
                    sk + (uint32_t)(((b_row + t * 16) * 20 + kt * 8 + b_cb) * 4));
        #pragma unroll
        for (int nt = 0; nt < 6; nt++)
            mma_bf16(sacc[nt], qa[0], qa[1], qa[2], qa[3], kb[nt * 2], kb[nt * 2 + 1]);
    }

    const float scale = 0.20412414523193154f;
    float m0 = -1e30f, m1 = -1e30f;
    #pragma unroll
    for (int nt = 0; nt < 6; nt++) {
        int j0 = nt * 8 + (lane & 3) * 2;
        float mv0 = mf[p][j0], mv1 = mf[p][j0 + 1];
        sacc[nt][0] = sacc[nt][0] * scale + mv0;
        sacc[nt][1] = sacc[nt][1] * scale + mv1;
        sacc[nt][2] = sacc[nt][2] * scale + mv0;
        sacc[nt][3] = sacc[nt][3] * scale + mv1;
        m0 = fmaxf(m0, fmaxf(sacc[nt][0], sacc[nt][1]));
        m1 = fmaxf(m1, fmaxf(sacc[nt][2], sacc[nt][3]));
    }
    m0 = fmaxf(m0, __shfl_xor_sync(0xFFFFFFFFu, m0, 1));
    m0 = fmaxf(m0, __shfl_xor_sync(0xFFFFFFFFu, m0, 2));
    m1 = fmaxf(m1, __shfl_xor_sync(0xFFFFFFFFu, m1, 1));
    m1 = fmaxf(m1, __shfl_xor_sync(0xFFFFFFFFu, m1, 2));
    float s0 = 0.f, s1 = 0.f;
    #pragma unroll
    for (int nt = 0; nt < 6; nt++) {
        sacc[nt][0] = __expf(sacc[nt][0] - m0);
        sacc[nt][1] = __expf(sacc[nt][1] - m0);
        sacc[nt][2] = __expf(sacc[nt][2] - m1);
        sacc[nt][3] = __expf(sacc[nt][3] - m1);
        s0 += sacc[nt][0] + sacc[nt][1];
        s1 += sacc[nt][2] + sacc[nt][3];
    }
    s0 += __shfl_xor_sync(0xFFFFFFFFu, s0, 1);
    s0 += __shfl_xor_sync(0xFFFFFFFFu, s0, 2);
    s1 += __shfl_xor_sync(0xFFFFFFFFu, s1, 1);
    s1 += __shfl_xor_sync(0xFFFFFFFFu, s1, 2);
    float i0 = 1.f / s0, i1 = 1.f / s1;
    #pragma unroll
    for (int nt = 0; nt < 6; nt++) {
        sacc[nt][0] *= i0; sacc[nt][1] *= i0;
        sacc[nt][2] *= i1; sacc[nt][3] *= i1;
    }

    uint32_t pah[3][4], pal[3][4];
    #pragma unroll
    for (int kt = 0; kt < 3; kt++) {
        const float* t0 = sacc[2 * kt];
        const float* t1 = sacc[2 * kt + 1];
        float src4[4][2] = {{t0[0], t0[1]}, {t0[2], t0[3]}, {t1[0], t1[1]}, {t1[2], t1[3]}};
        #pragma unroll
        for (int r = 0; r < 4; r++) {
            __nv_bfloat162 hh = __floats2bfloat162_rn(src4[r][0], src4[r][1]);
            pah[kt][r] = *reinterpret_cast<const uint32_t*>(&hh);
            float lx = src4[r][0] - __bfloat162float(hh.x);
            float ly = src4[r][1] - __bfloat162float(hh.y);
            pal[kt][r] = pack_bf16(lx, ly);
        }
    }

    float oacc[3][4];
    #pragma unroll
    for (int d = 0; d < 3; d++)
        #pragma unroll
        for (int i = 0; i < 4; i++) oacc[d][i] = 0.f;

    const int v_row = (lane & 7) + ((lane >> 3) & 1) * 8;
    const int v_cb  = ((lane >> 4) & 1) * 4;
    #pragma unroll
    for (int kt = 0; kt < 3; kt++) {
        uint32_t base = svv + (uint32_t)(((16 * kt + v_row) * 20 + v_cb) * 4);
        uint32_t b0[4], b1[4];
        ldsm_x4_t(b0[0], b0[1], b0[2], b0[3], base);
        ldsm_x4_t(b1[0], b1[1], b1[2], b1[3], base + 32);
        mma_bf16(oacc[0], pah[kt][0], pah[kt][1], pah[kt][2], pah[kt][3], b0[0], b0[1]);
        mma_bf16(oacc[0], pal[kt][0], pal[kt][1], pal[kt][2], pal[kt][3], b0[0], b0[1]);
        mma_bf16(oacc[1], pah[kt][0], pah[kt][1], pah[kt][2], pah[kt][3], b0[2], b0[3]);
        mma_bf16(oacc[1], pal[kt][0], pal[kt][1], pal[kt][2], pal[kt][3], b0[2], b0[3]);
        mma_bf16(oacc[2], pah[kt][0], pah[kt][1], pah[kt][2], pah[kt][3], b1[0], b1[1]);
        mma_bf16(oacc[2], pal[kt][0], pal[kt][1], pal[kt][2], pal[kt][3], b1[0], b1[1]);
    }

    {
        size_t r0 = (size_t)s * SETSZ + w * 16 + (lane >> 2);
        int dbase = h * HD + (lane & 3) * 2;
        #pragma unroll
        for (int db = 0; db < 3; db++) {
            int dd = dbase + db * 8;
            *(uint32_t*)&g_ctx[r0 * CDIM + dd]       = pack_bf16(oacc[db][0], oacc[db][1]);
            *(uint32_t*)&g_ctx[(r0 + 8) * CDIM + dd] = pack_bf16(oacc[db][2], oacc[db][3]);
        }
    }
}

// ---------------- launch --------------------------------------------------
extern "C" void kernel_launch(void* const* d_in, const int* in_sizes, int n_in,
                              void* d_out, int out_size)
{
    const float* src   = (const float*)d_in[0];
    const float* pos   = (const float*)d_in[1];
    const float* w_qkv = (const float*)d_in[2];
    const float* b_qkv = (const float*)d_in[3];
    const float* w_out = (const float*)d_in[4];
    const float* b_out = (const float*)d_in[5];
    const float* w1    = (const float*)d_in[6];
    const float* b1    = (const float*)d_in[7];
    const float* w2    = (const float*)d_in[8];
    const float* b2    = (const float*)d_in[9];
    const float* ln1g  = (const float*)d_in[10];
    const float* ln1b  = (const float*)d_in[11];
    const float* ln2g  = (const float*)d_in[12];
    const float* ln2b  = (const float*)d_in[13];
    const float* ln3g  = (const float*)d_in[14];
    const float* ln3b  = (const float*)d_in[15];
    const int*   vidx  = (const int*)d_in[16];
    const uint8_t* msk = (const uint8_t*)d_in[17];
    float* out = (float*)d_out;

    __nv_bfloat16 *p_ctx, *p_xb, *p_h;
    __nv_bfloat16 *p_wqkv, *p_wout, *p_w1, *p_w2;
    float *p_x;
    cudaGetSymbolAddress((void**)&p_ctx,  g_ctx);
    cudaGetSymbolAddress((void**)&p_x,    g_x);
    cudaGetSymbolAddress((void**)&p_xb,   g_xb);
    cudaGetSymbolAddress((void**)&p_h,    g_h);
    cudaGetSymbolAddress((void**)&p_wqkv, g_wqkv);
    cudaGetSymbolAddress((void**)&p_wout, g_wout);
    cudaGetSymbolAddress((void**)&p_w1,   g_w1);
    cudaGetSymbolAddress((void**)&p_w2,   g_w2);

    cudaFuncSetAttribute(qkv_fused,  cudaFuncAttributeMaxDynamicSharedMemorySize, QK_SMEM);
    cudaFuncSetAttribute(ffn1_fused, cudaFuncAttributeMaxDynamicSharedMemorySize, F1_SMEM);
    cudaFuncSetAttribute(gemm_bf16<0,1>, cudaFuncAttributeMaxDynamicSharedMemorySize, GEMM_SMEM_BYTES);
    cudaFuncSetAttribute(gemm_bf16<0,2>, cudaFuncAttributeMaxDynamicSharedMemorySize, GEMM_SMEM_BYTES);

    // 0) all weights -> bf16 (single launch)
    {
        int total = CVT_N0 + CVT_N1 + CVT_N2 + CVT_N3;
        cvt_all<<<(total + 255) / 256, 256>>>(w_qkv, w_out, w1, w2);
    }

    const int MB = NVOX / 64;  // 3072

    // 1) fused gather + q,k,v projections (2 CTAs/SM)
    qkv_fused<<<MB, 256, QK_SMEM>>>(src, pos, vidx, p_wqkv, b_qkv);

    // 2) attention (tensor cores)
    attn_kernel<<<(SETS * NHEAD) / 2, 192>>>(msk);

    // 3) out-proj + scatter + residual + LN1 -> g_x (fp32) + g_xb (bf16)
    gemm_bf16<0,1><<<dim3(MB, 1), 256, GEMM_SMEM_BYTES>>>(
        p_ctx, p_wout, b_out, p_x, p_xb, vidx,
        src, nullptr, ln1g, ln1b, nullptr, nullptr,
        CDIM, CDIM);

    // 4) FFN1 (relu), xb staged once (2 CTAs/SM)
    ffn1_fused<<<MB, 256, F1_SMEM>>>(p_xb, p_w1, b1);

    // 5) FFN2 + LN2 + residual + LN3 -> out (fp32)
    gemm_bf16<0,2><<<dim3(MB, 1), 256, GEMM_SMEM_BYTES>>>(
        p_h, p_w2, b2, out, nullptr, nullptr,
        src, p_x, ln2g, ln2b, ln3g, ln3b,
        CDIM, DFF);
}

// round 17
// speedup vs baseline: 1.2253x; 1.0579x over previous
#include <cuda_runtime.h>
#include <cuda_bf16.h>
#include <cstdint>
#include <cstddef>

// ---------------- problem constants ----------------
#define NVOX   196608
#define CDIM   192
#define SETS   4096
#define SETSZ  48
#define NHEAD  8
#define HD     24
#define DFF    384

// ---------------- scratch (device globals) ----------------
__device__ __nv_bfloat16 g_qk [(size_t)NVOX * 2 * CDIM]; // q 0..191, k 192..383 (set-slot)
__device__ __nv_bfloat16 g_v  [(size_t)NVOX * CDIM];
__device__ __nv_bfloat16 g_ctx[(size_t)NVOX * CDIM];
__device__ __nv_bfloat16 g_xb [(size_t)NVOX * CDIM];     // LN1 out bf16, SET-SLOT order
__device__ __nv_bfloat16 g_h  [(size_t)NVOX * DFF];      // FFN hidden, set-slot order
// bf16 weights
__device__ __nv_bfloat16 g_wqkv[3 * CDIM * CDIM];
__device__ __nv_bfloat16 g_wout[CDIM * CDIM];
__device__ __nv_bfloat16 g_w1  [DFF * CDIM];
__device__ __nv_bfloat16 g_w2  [CDIM * DFF];

// ---------------- helpers ----------------
__device__ __forceinline__ uint32_t pack_bf16(float x, float y)
{
    __nv_bfloat162 h2 = __floats2bfloat162_rn(x, y);
    return *reinterpret_cast<const uint32_t*>(&h2);
}
__device__ __forceinline__ float2 unpack_bf16(uint32_t u)
{
    return __bfloat1622float2(*reinterpret_cast<__nv_bfloat162*>(&u));
}

__device__ __forceinline__ void mma_bf16(float c[4],
    uint32_t a0, uint32_t a1, uint32_t a2, uint32_t a3,
    uint32_t b0, uint32_t b1)
{
    asm volatile(
        "mma.sync.aligned.m16n8k16.row.col.f32.bf16.bf16.f32 "
        "{%0,%1,%2,%3}, {%4,%5,%6,%7}, {%8,%9}, {%0,%1,%2,%3};\n"
        : "+f"(c[0]), "+f"(c[1]), "+f"(c[2]), "+f"(c[3])
        : "r"(a0), "r"(a1), "r"(a2), "r"(a3), "r"(b0), "r"(b1));
}
__device__ __forceinline__ void ldsm_x4(uint32_t& r0, uint32_t& r1,
                                        uint32_t& r2, uint32_t& r3, uint32_t addr)
{
    asm volatile("ldmatrix.sync.aligned.m8n8.x4.shared.b16 {%0,%1,%2,%3}, [%4];"
                 : "=r"(r0), "=r"(r1), "=r"(r2), "=r"(r3) : "r"(addr));
}
__device__ __forceinline__ void ldsm_x4_t(uint32_t& r0, uint32_t& r1,
                                          uint32_t& r2, uint32_t& r3, uint32_t addr)
{
    asm volatile("ldmatrix.sync.aligned.m8n8.x4.trans.shared.b16 {%0,%1,%2,%3}, [%4];"
                 : "=r"(r0), "=r"(r1), "=r"(r2), "=r"(r3) : "r"(addr));
}
__device__ __forceinline__ void cp16(uint32_t saddr, const void* gaddr)
{
    asm volatile("cp.async.cg.shared.global [%0], [%1], 16;"
                 :: "r"(saddr), "l"(gaddr) : "memory");
}
#define CP_COMMIT() asm volatile("cp.async.commit_group;" ::: "memory")
#define CP_WAIT1()  asm volatile("cp.async.wait_group 1;" ::: "memory")
#define CP_WAIT0()  asm volatile("cp.async.wait_group 0;" ::: "memory")

// ---------------- all-weights fp32 -> bf16 conversion ----------------------
#define CVT_N0 (3 * CDIM * CDIM / 2)
#define CVT_N1 (CDIM * CDIM / 2)
#define CVT_N2 (DFF * CDIM / 2)
#define CVT_N3 (CDIM * DFF / 2)
__global__ void cvt_all(const float* __restrict__ a, const float* __restrict__ b,
                        const float* __restrict__ c, const float* __restrict__ d)
{
    int i = blockIdx.x * blockDim.x + threadIdx.x;
    if (i < CVT_N0) {
        ((uint32_t*)g_wqkv)[i] = pack_bf16(a[2 * i], a[2 * i + 1]);
    } else if (i < CVT_N0 + CVT_N1) {
        int j = i - CVT_N0;
        ((uint32_t*)g_wout)[j] = pack_bf16(b[2 * j], b[2 * j + 1]);
    } else if (i < CVT_N0 + CVT_N1 + CVT_N2) {
        int j = i - CVT_N0 - CVT_N1;
        ((uint32_t*)g_w1)[j] = pack_bf16(c[2 * j], c[2 * j + 1]);
    } else if (i < CVT_N0 + CVT_N1 + CVT_N2 + CVT_N3) {
        int j = i - CVT_N0 - CVT_N1 - CVT_N2;
        ((uint32_t*)g_w2)[j] = pack_bf16(d[2 * j], d[2 * j + 1]);
    }
}

// ---------------- fused gather + QKV projection (2 CTAs/SM) ----------------
#define QK_XQ 0
#define QK_XV 30720
#define QK_WS 61440
#define QK_WSTG 15360
#define QK_SV (QK_WS + 2 * QK_WSTG)
#define QK_SMEM (QK_SV + 256)

__global__ void __launch_bounds__(256, 2)
qkv_fused(const float* __restrict__ src, const float* __restrict__ pos,
          const int* __restrict__ vidx,
          const __nv_bfloat16* __restrict__ wqkv, const float* __restrict__ bqkv)
{
    extern __shared__ char smem[];
    const uint32_t sbase = (uint32_t)__cvta_generic_to_shared(smem);
    int* sv = (int*)(smem + QK_SV);

    const int tid  = threadIdx.x;
    const int lane = tid & 31;
    const int warp = tid >> 5;
    const int wr   = warp >> 2;
    const int wc   = warp & 3;
    const int row0 = blockIdx.x * 64;

    if (tid < 64) sv[tid] = vidx[row0 + tid];
    __syncthreads();

    const int arow = tid >> 2;
    const int ach  = tid & 3;

    {
        int v = sv[arow];
        const float* srow = src + (size_t)v * CDIM;
        const float* prow = pos + (size_t)v * CDIM;
        #pragma unroll
        for (int c = 0; c < 6; c++) {
            int col = c * 32 + ach * 8;
            float4 s0 = *(const float4*)(srow + col);
            float4 s1 = *(const float4*)(srow + col + 4);
            float4 p0 = *(const float4*)(prow + col);
            float4 p1 = *(const float4*)(prow + col + 4);
            uint4 fv, qv;
            fv.x = pack_bf16(s0.x, s0.y); fv.y = pack_bf16(s0.z, s0.w);
            fv.z = pack_bf16(s1.x, s1.y); fv.w = pack_bf16(s1.z, s1.w);
            qv.x = pack_bf16(s0.x + p0.x, s0.y + p0.y);
            qv.y = pack_bf16(s0.z + p0.z, s0.w + p0.w);
            qv.z = pack_bf16(s1.x + p1.x, s1.y + p1.y);
            qv.w = pack_bf16(s1.z + p1.z, s1.w + p1.w);
            *(uint4*)(smem + QK_XV + c * 5120 + arow * 80 + ach * 16) = fv;
            *(uint4*)(smem + QK_XQ + c * 5120 + arow * 80 + ach * 16) = qv;
        }
    }
    __syncthreads();

    const int a_row = wr * 32 + (lane & 7) + ((lane >> 3) & 1) * 8;
    const int a_cb  = ((lane >> 4) & 1) * 4;
    const int b_row = wc * 48 + (lane & 7) + ((lane >> 4) & 1) * 8;
    const int b_cb  = ((lane >> 3) & 1) * 4;

    #pragma unroll 1
    for (int g = 0; g < 3; g++) {
        const __nv_bfloat16* W = wqkv + (size_t)g * 192 * CDIM;
        const uint32_t xbase = sbase + (g == 2 ? QK_XV : QK_XQ);

        auto issueW = [&](int kc) {
            uint32_t sW = sbase + QK_WS + (kc & 1) * QK_WSTG;
            #pragma unroll
            for (int r = 0; r < 3; r++) {
                int rr = arow + r * 64;
                cp16(sW + rr * 80 + ach * 16, W + (size_t)rr * CDIM + kc * 32 + ach * 8);
            }
            CP_COMMIT();
        };
        issueW(0);

        float acc[2][6][4];
        #pragma unroll
        for (int m = 0; m < 2; m++)
            #pragma unroll
            for (int n = 0; n < 6; n++)
                #pragma unroll
                for (int i = 0; i < 4; i++) acc[m][n][i] = 0.f;

        for (int kc = 0; kc < 6; kc++) {
            if (kc + 1 < 6) { issueW(kc + 1); CP_WAIT1(); }
            else            { CP_WAIT0(); }
            __syncthreads();

            const uint32_t stA = xbase + kc * 5120;
            const uint32_t stB = sbase + QK_WS + (kc & 1) * QK_WSTG;
            #pragma unroll
            for (int k16 = 0; k16 < 2; k16++) {
                const int kp = k16 * 8;
                uint32_t ah[4], ah2[4];
                ldsm_x4(ah[0], ah[1], ah[2], ah[3],
                        stA + (uint32_t)((a_row * 20 + kp + a_cb) * 4));
                ldsm_x4(ah2[0], ah2[1], ah2[2], ah2[3],
                        stA + (uint32_t)(((a_row + 16) * 20 + kp + a_cb) * 4));
                uint32_t bh[12];
                #pragma unroll
                for (int p = 0; p < 3; p++) {
                    ldsm_x4(bh[p * 4 + 0], bh[p * 4 + 1], bh[p * 4 + 2], bh[p * 4 + 3],
                            stB + (uint32_t)(((b_row + p * 16) * 20 + kp + b_cb) * 4));
                }
                #pragma unroll
                for (int nt = 0; nt < 6; nt++) {
                    uint32_t bh0 = bh[nt * 2], bh1 = bh[nt * 2 + 1];
                    mma_bf16(acc[0][nt], ah[0],  ah[1],  ah[2],  ah[3],  bh0, bh1);
                    mma_bf16(acc[1][nt], ah2[0], ah2[1], ah2[2], ah2[3], bh0, bh1);
                }
            }
            __syncthreads();
        }

        const float* bias = bqkv + g * 192;
        __nv_bfloat16* C = (g < 2) ? g_qk : g_v;
        const int ldC  = (g < 2) ? 2 * CDIM : CDIM;
        const int coff = (g == 1) ? CDIM : 0;
        #pragma unroll
        for (int mt = 0; mt < 2; mt++) {
            int r0 = row0 + wr * 32 + mt * 16 + (lane >> 2);
            #pragma unroll
            for (int nt = 0; nt < 6; nt++) {
                int c = wc * 48 + nt * 8 + 2 * (lane & 3);
                float bx = bias[c], by = bias[c + 1];
                float o0x = acc[mt][nt][0] + bx, o0y = acc[mt][nt][1] + by;
                float o1x = acc[mt][nt][2] + bx, o1y = acc[mt][nt][3] + by;
                *(uint32_t*)&C[(size_t)r0 * ldC + coff + c]       = pack_bf16(o0x, o0y);
                *(uint32_t*)&C[(size_t)(r0 + 8) * ldC + coff + c] = pack_bf16(o1x, o1y);
            }
        }
    }
}

// ---- fused out-proj + LN1 + FFN1; all in set-slot order -------------------
// Phase A: acc = ctx @ wout^T (3-stage). LN1(acc+b + src[vidx]) -> xb (global,
// coalesced) + smem chunks. Phase B: h = relu(x @ W1^T + b1) -> g_h.
#define OP_W1 30720
#define OP_RS 61440
#define OP_SV 61952
#define OP_SMEM 62208

__global__ void __launch_bounds__(256, 2)
oproj_ffn1(const __nv_bfloat16* __restrict__ ctx, const __nv_bfloat16* __restrict__ wout,
           const float* __restrict__ bout,
           const int* __restrict__ vidx, const float* __restrict__ src,
           const float* __restrict__ ln1g, const float* __restrict__ ln1b,
           const __nv_bfloat16* __restrict__ w1, const float* __restrict__ b1)
{
    extern __shared__ char smem[];
    const uint32_t sbase = (uint32_t)__cvta_generic_to_shared(smem);
    int* sv = (int*)(smem + OP_SV);

    const int tid  = threadIdx.x;
    const int lane = tid & 31;
    const int warp = tid >> 5;
    const int wr   = warp >> 2;
    const int wc   = warp & 3;
    const int row0 = blockIdx.x * 64;

    if (tid < 64) sv[tid] = vidx[row0 + tid];

    const int arow = tid >> 2;
    const int ach  = tid & 3;

    const __nv_bfloat16* Arow = ctx + (size_t)row0 * CDIM;

    auto issue = [&](int it) {
        int st = it % 3;
        uint32_t sA = sbase + st * 20480;
        int kb = it * 32;
        cp16(sA + arow * 80 + ach * 16, Arow + (size_t)arow * CDIM + kb + ach * 8);
        uint32_t sB = sA + 5120;
        #pragma unroll
        for (int r = 0; r < 3; r++) {
            int rr = arow + r * 64;
            cp16(sB + rr * 80 + ach * 16, wout + (size_t)rr * CDIM + kb + ach * 8);
        }
        CP_COMMIT();
    };

    const int a_row = wr * 32 + (lane & 7) + ((lane >> 3) & 1) * 8;
    const int a_cb  = ((lane >> 4) & 1) * 4;
    const int b_row = wc * 48 + (lane & 7) + ((lane >> 4) & 1) * 8;
    const int b_cb  = ((lane >> 3) & 1) * 4;

    float acc[2][6][4];
    #pragma unroll
    for (int m = 0; m < 2; m++)
        #pragma unroll
        for (int n = 0; n < 6; n++)
            #pragma unroll
            for (int i = 0; i < 4; i++) acc[m][n][i] = 0.f;

    issue(0); issue(1);
    for (int it = 0; it < 6; it++) {
        CP_WAIT1();
        __syncthreads();
        if (it + 2 < 6) issue(it + 2);
        else CP_COMMIT();

        const uint32_t stA = sbase + (it % 3) * 20480;
        const uint32_t stB = stA + 5120;
        #pragma unroll
        for (int k16 = 0; k16 < 2; k16++) {
            const int kp = k16 * 8;
            uint32_t ah[4], ah2[4];
            ldsm_x4(ah[0], ah[1], ah[2], ah[3],
                    stA + (uint32_t)((a_row * 20 + kp + a_cb) * 4));
            ldsm_x4(ah2[0], ah2[1], ah2[2], ah2[3],
                    stA + (uint32_t)(((a_row + 16) * 20 + kp + a_cb) * 4));
            uint32_t bh[12];
            #pragma unroll
            for (int p = 0; p < 3; p++) {
                ldsm_x4(bh[p * 4 + 0], bh[p * 4 + 1], bh[p * 4 + 2], bh[p * 4 + 3],
                        stB + (uint32_t)(((b_row + p * 16) * 20 + kp + b_cb) * 4));
            }
            #pragma unroll
            for (int nt = 0; nt < 6; nt++) {
                uint32_t bh0 = bh[nt * 2], bh1 = bh[nt * 2 + 1];
                mma_bf16(acc[0][nt], ah[0],  ah[1],  ah[2],  ah[3],  bh0, bh1);
                mma_bf16(acc[1][nt], ah2[0], ah2[1], ah2[2], ah2[3], bh0, bh1);
            }
        }
        __syncthreads();
    }

    // ---- LN1 epilogue (rows stay in set-slot order) ----
    float* rsum = (float*)(smem + OP_RS);
    float* rsq  = rsum + 64;
    if (tid < 64) { rsum[tid] = 0.f; rsq[tid] = 0.f; }
    __syncthreads();

    #pragma unroll
    for (int mt = 0; mt < 2; mt++) {
        #pragma unroll
        for (int half = 0; half < 2; half++) {
            int row = wr * 32 + mt * 16 + (lane >> 2) + half * 8;
            int v = sv[row];
            float s1 = 0.f, s2 = 0.f;
            #pragma unroll
            for (int nt = 0; nt < 6; nt++) {
                int c = wc * 48 + nt * 8 + 2 * (lane & 3);
                float2 res = *(const float2*)&src[(size_t)v * CDIM + c];
                float v0 = acc[mt][nt][half * 2 + 0] + bout[c]     + res.x;
                float v1 = acc[mt][nt][half * 2 + 1] + bout[c + 1] + res.y;
                acc[mt][nt][half * 2 + 0] = v0;
                acc[mt][nt][half * 2 + 1] = v1;
                s1 += v0 + v1; s2 += v0 * v0 + v1 * v1;
            }
            atomicAdd(&rsum[row], s1);
            atomicAdd(&rsq[row],  s2);
        }
    }
    __syncthreads();

    #pragma unroll
    for (int mt = 0; mt < 2; mt++) {
        #pragma unroll
        for (int half = 0; half < 2; half++) {
            int row = wr * 32 + mt * 16 + (lane >> 2) + half * 8;
            float mean = rsum[row] * (1.f / CDIM);
            float var  = rsq[row] * (1.f / CDIM) - mean * mean;
            float inv  = rsqrtf(var + 1e-5f);
            #pragma unroll
            for (int nt = 0; nt < 6; nt++) {
                int c = wc * 48 + nt * 8 + 2 * (lane & 3);
                float x0 = (acc[mt][nt][half * 2 + 0] - mean) * inv * ln1g[c]     + ln1b[c];
                float x1 = (acc[mt][nt][half * 2 + 1] - mean) * inv * ln1g[c + 1] + ln1b[c + 1];
                uint32_t pk = pack_bf16(x0, x1);
                *(uint32_t*)&g_xb[(size_t)(row0 + row) * CDIM + c] = pk;
                *(uint32_t*)(smem + (c >> 5) * 5120 + row * 80 + (c & 31) * 2) = pk;
            }
        }
    }
    __syncthreads();

    // ---- phase B: FFN1 (x chunks at smem[0..30720), W1 2-stage) ----
    #pragma unroll 1
    for (int g = 0; g < 2; g++) {
        const __nv_bfloat16* W = w1 + (size_t)g * 192 * CDIM;
        auto issueW = [&](int kc) {
            uint32_t sW = sbase + OP_W1 + (kc & 1) * 15360;
            #pragma unroll
            for (int r = 0; r < 3; r++) {
                int rr = arow + r * 64;
                cp16(sW + rr * 80 + ach * 16, W + (size_t)rr * CDIM + kc * 32 + ach * 8);
            }
            CP_COMMIT();
        };
        issueW(0);

        float facc[2][6][4];
        #pragma unroll
        for (int m = 0; m < 2; m++)
            #pragma unroll
            for (int n = 0; n < 6; n++)
                #pragma unroll
                for (int i = 0; i < 4; i++) facc[m][n][i] = 0.f;

        for (int kc = 0; kc < 6; kc++) {
            if (kc + 1 < 6) { issueW(kc + 1); CP_WAIT1(); }
            else            { CP_WAIT0(); }
            __syncthreads();

            const uint32_t stA = sbase + kc * 5120;
            const uint32_t stB = sbase + OP_W1 + (kc & 1) * 15360;
            #pragma unroll
            for (int k16 = 0; k16 < 2; k16++) {
                const int kp = k16 * 8;
                uint32_t ah[4], ah2[4];
                ldsm_x4(ah[0], ah[1], ah[2], ah[3],
                        stA + (uint32_t)((a_row * 20 + kp + a_cb) * 4));
                ldsm_x4(ah2[0], ah2[1], ah2[2], ah2[3],
                        stA + (uint32_t)(((a_row + 16) * 20 + kp + a_cb) * 4));
                uint32_t bh[12];
                #pragma unroll
                for (int p = 0; p < 3; p++) {
                    ldsm_x4(bh[p * 4 + 0], bh[p * 4 + 1], bh[p * 4 + 2], bh[p * 4 + 3],
                            stB + (uint32_t)(((b_row + p * 16) * 20 + kp + b_cb) * 4));
                }
                #pragma unroll
                for (int nt = 0; nt < 6; nt++) {
                    uint32_t bh0 = bh[nt * 2], bh1 = bh[nt * 2 + 1];
                    mma_bf16(facc[0][nt], ah[0],  ah[1],  ah[2],  ah[3],  bh0, bh1);
                    mma_bf16(facc[1][nt], ah2[0], ah2[1], ah2[2], ah2[3], bh0, bh1);
                }
            }
            __syncthreads();
        }

        const float* bias = b1 + g * 192;
        #pragma unroll
        for (int mt = 0; mt < 2; mt++) {
            int r0 = row0 + wr * 32 + mt * 16 + (lane >> 2);
            #pragma unroll
            for (int nt = 0; nt < 6; nt++) {
                int c = wc * 48 + nt * 8 + 2 * (lane & 3);
                float bx = bias[c], by = bias[c + 1];
                float o0x = fmaxf(facc[mt][nt][0] + bx, 0.f);
                float o0y = fmaxf(facc[mt][nt][1] + by, 0.f);
                float o1x = fmaxf(facc[mt][nt][2] + bx, 0.f);
                float o1y = fmaxf(facc[mt][nt][3] + by, 0.f);
                *(uint32_t*)&g_h[(size_t)r0 * DFF + g * 192 + c]       = pack_bf16(o0x, o0y);
                *(uint32_t*)&g_h[(size_t)(r0 + 8) * DFF + g * 192 + c] = pack_bf16(o1x, o1y);
            }
        }
    }
}

// ---- FFN2 + LN2(+xb) + src residual + LN3, scatter to voxel order ---------
#define F2_STAGE 20480
#define F2_SV (3 * F2_STAGE)
#define F2_SMEM (F2_SV + 256)

__global__ void __launch_bounds__(256, 2)
ffn2(const __nv_bfloat16* __restrict__ h, const __nv_bfloat16* __restrict__ w2,
     const float* __restrict__ b2,
     const int* __restrict__ vidx, const float* __restrict__ src,
     const __nv_bfloat16* __restrict__ xb,
     const float* __restrict__ ln2g, const float* __restrict__ ln2b,
     const float* __restrict__ ln3g, const float* __restrict__ ln3b,
     float* __restrict__ outp)
{
    extern __shared__ char smem[];
    const uint32_t sbase = (uint32_t)__cvta_generic_to_shared(smem);
    int* sv = (int*)(smem + F2_SV);

    const int tid  = threadIdx.x;
    const int lane = tid & 31;
    const int warp = tid >> 5;
    const int wr   = warp >> 2;
    const int wc   = warp & 3;
    const int row0 = blockIdx.x * 64;

    if (tid < 64) sv[tid] = vidx[row0 + tid];

    const __nv_bfloat16* Arow = h + (size_t)row0 * DFF;
    const int arow = tid >> 2;
    const int ach  = tid & 3;

    auto issue = [&](int it) {
        int st = it % 3;
        uint32_t sA = sbase + st * F2_STAGE;
        int kb = it * 32;
        cp16(sA + arow * 80 + ach * 16, Arow + (size_t)arow * DFF + kb + ach * 8);
        uint32_t sB = sA + 5120;
        #pragma unroll
        for (int r = 0; r < 3; r++) {
            int rr = arow + r * 64;
            cp16(sB + rr * 80 + ach * 16, w2 + (size_t)rr * DFF + kb + ach * 8);
        }
        CP_COMMIT();
    };

    const int a_row = wr * 32 + (lane & 7) + ((lane >> 3) & 1) * 8;
    const int a_cb  = ((lane >> 4) & 1) * 4;
    const int b_row = wc * 48 + (lane & 7) + ((lane >> 4) & 1) * 8;
    const int b_cb  = ((lane >> 3) & 1) * 4;

    float acc[2][6][4];
    #pragma unroll
    for (int m = 0; m < 2; m++)
        #pragma unroll
        for (int n = 0; n < 6; n++)
            #pragma unroll
            for (int i = 0; i < 4; i++) acc[m][n][i] = 0.f;

    issue(0); issue(1);
    for (int it = 0; it < 12; it++) {
        CP_WAIT1();
        __syncthreads();
        if (it + 2 < 12) issue(it + 2);
        else CP_COMMIT();

        const uint32_t stA = sbase + (it % 3) * F2_STAGE;
        const uint32_t stB = stA + 5120;
        #pragma unroll
        for (int k16 = 0; k16 < 2; k16++) {
            const int kp = k16 * 8;
            uint32_t ah[4], ah2[4];
            ldsm_x4(ah[0], ah[1], ah[2], ah[3],
                    stA + (uint32_t)((a_row * 20 + kp + a_cb) * 4));
            ldsm_x4(ah2[0], ah2[1], ah2[2], ah2[3],
                    stA + (uint32_t)(((a_row + 16) * 20 + kp + a_cb) * 4));
            uint32_t bh[12];
            #pragma unroll
            for (int p = 0; p < 3; p++) {
                ldsm_x4(bh[p * 4 + 0], bh[p * 4 + 1], bh[p * 4 + 2], bh[p * 4 + 3],
                        stB + (uint32_t)(((b_row + p * 16) * 20 + kp + b_cb) * 4));
            }
            #pragma unroll
            for (int nt = 0; nt < 6; nt++) {
                uint32_t bh0 = bh[nt * 2], bh1 = bh[nt * 2 + 1];
                mma_bf16(acc[0][nt], ah[0],  ah[1],  ah[2],  ah[3],  bh0, bh1);
                mma_bf16(acc[1][nt], ah2[0], ah2[1], ah2[2], ah2[3], bh0, bh1);
            }
        }
        __syncthreads();
    }

    // ---- LN2(acc + b2 + xb) -> + src[v] -> LN3 -> out[v] ----
    float* rsum = (float*)smem;
    float* rsq  = (float*)smem + 64;
    if (tid < 64) { rsum[tid] = 0.f; rsq[tid] = 0.f; }
    __syncthreads();

    #pragma unroll
    for (int mt = 0; mt < 2; mt++) {
        #pragma unroll
        for (int half = 0; half < 2; half++) {
            int row = wr * 32 + mt * 16 + (lane >> 2) + half * 8;
            float s1 = 0.f, s2 = 0.f;
            #pragma unroll
            for (int nt = 0; nt < 6; nt++) {
                int c = wc * 48 + nt * 8 + 2 * (lane & 3);
                float2 res = unpack_bf16(*(const uint32_t*)&xb[(size_t)(row0 + row) * CDIM + c]);
                float v0 = acc[mt][nt][half * 2 + 0] + b2[c]     + res.x;
                float v1 = acc[mt][nt][half * 2 + 1] + b2[c + 1] + res.y;
                acc[mt][nt][half * 2 + 0] = v0;
                acc[mt][nt][half * 2 + 1] = v1;
                s1 += v0 + v1; s2 += v0 * v0 + v1 * v1;
            }
            atomicAdd(&rsum[row], s1);
            atomicAdd(&rsq[row],  s2);
        }
    }
    __syncthreads();

    float su1[4], su2[4];
    #pragma unroll
    for (int mt = 0; mt < 2; mt++) {
        #pragma unroll
        for (int half = 0; half < 2; half++) {
            int row = wr * 32 + mt * 16 + (lane >> 2) + half * 8;
            int v = sv[row];
            float mean = rsum[row] * (1.f / CDIM);
            float var  = rsq[row] * (1.f / CDIM) - mean * mean;
            float inv  = rsqrtf(var + 1e-5f);
            float s1 = 0.f, s2 = 0.f;
            #pragma unroll
            for (int nt = 0; nt < 6; nt++) {
                int c = wc * 48 + nt * 8 + 2 * (lane & 3);
                float2 sr = *(const float2*)&src[(size_t)v * CDIM + c];
                float u0 = (acc[mt][nt][half * 2 + 0] - mean) * inv * ln2g[c]     + ln2b[c]     + sr.x;
                float u1 = (acc[mt][nt][half * 2 + 1] - mean) * inv * ln2g[c + 1] + ln2b[c + 1] + sr.y;
                acc[mt][nt][half * 2 + 0] = u0;
                acc[mt][nt][half * 2 + 1] = u1;
                s1 += u0 + u1; s2 += u0 * u0 + u1 * u1;
            }
            su1[mt * 2 + half] = s1;
            su2[mt * 2 + half] = s2;
        }
    }
    __syncthreads();
    if (tid < 64) { rsum[tid] = 0.f; rsq[tid] = 0.f; }
    __syncthreads();
    #pragma unroll
    for (int mt = 0; mt < 2; mt++) {
        #pragma unroll
        for (int half = 0; half < 2; half++) {
            int row = wr * 32 + mt * 16 + (lane >> 2) + half * 8;
            atomicAdd(&rsum[row], su1[mt * 2 + half]);
            atomicAdd(&rsq[row],  su2[mt * 2 + half]);
        }
    }
    __syncthreads();
    #pragma unroll
    for (int mt = 0; mt < 2; mt++) {
        #pragma unroll
        for (int half = 0; half < 2; half++) {
            int row = wr * 32 + mt * 16 + (lane >> 2) + half * 8;
            int v = sv[row];
            float mean = rsum[row] * (1.f / CDIM);
            float var  = rsq[row] * (1.f / CDIM) - mean * mean;
            float inv  = rsqrtf(var + 1e-5f);
            #pragma unroll
            for (int nt = 0; nt < 6; nt++) {
                int c = wc * 48 + nt * 8 + 2 * (lane & 3);
                float2 o;
                o.x = (acc[mt][nt][half * 2 + 0] - mean) * inv * ln3g[c]     + ln3b[c];
                o.y = (acc[mt][nt][half * 2 + 1] - mean) * inv * ln3g[c + 1] + ln3b[c + 1];
                *(float2*)&outp[(size_t)v * CDIM + c] = o;
            }
        }
    }
}

// ---------------- attention (tensor-core): 192 thr = 2 pairs x 3 warps ------
__global__ void __launch_bounds__(192)
attn_kernel(const uint8_t* __restrict__ mask)
{
    __shared__ __nv_bfloat16 qs[2][SETSZ][40];
    __shared__ __nv_bfloat16 ks[2][SETSZ][40];
    __shared__ __nv_bfloat16 vs[2][SETSZ][40];
    __shared__ float mf[2][SETSZ];

    const int tid  = threadIdx.x;
    const int lane = tid & 31;
    const int warp = tid >> 5;
    const int p    = warp / 3;
    const int w    = warp % 3;

    {
        int lt = tid % 96;
        int pp = tid / 96;
        int gpp = blockIdx.x * 2 + pp;
        int ss = gpp >> 3, hh = gpp & 7;
        for (int task = lt; task < SETSZ * 3; task += 96) {
            int row = task / 3, ch = task % 3;
            size_t ro = (size_t)ss * SETSZ + row;
            const __nv_bfloat16* qrow = g_qk + ro * (2 * CDIM) + (size_t)hh * HD + ch * 8;
            *(uint4*)&qs[pp][row][ch * 8] = *(const uint4*)qrow;
            *(uint4*)&ks[pp][row][ch * 8] = *(const uint4*)(qrow + CDIM);
            *(uint4*)&vs[pp][row][ch * 8] = *(const uint4*)(g_v + ro * CDIM + (size_t)hh * HD + ch * 8);
        }
        for (int row = lt; row < SETSZ; row += 96) {
            *(uint4*)&qs[pp][row][24] = make_uint4(0, 0, 0, 0);
            *(uint4*)&ks[pp][row][24] = make_uint4(0, 0, 0, 0);
            *(uint4*)&vs[pp][row][24] = make_uint4(0, 0, 0, 0);
            mf[pp][row] = (mask[(size_t)ss * SETSZ + row] != 0) ? -1e9f : 0.f;
        }
    }
    __syncthreads();

    const int gp = blockIdx.x * 2 + p;
    const int s  = gp >> 3;
    const int h  = gp & 7;

    const uint32_t sq = (uint32_t)__cvta_generic_to_shared(&qs[p][0][0]);
    const uint32_t sk = (uint32_t)__cvta_generic_to_shared(&ks[p][0][0]);
    const uint32_t svv = (uint32_t)__cvta_generic_to_shared(&vs[p][0][0]);

    const int a_row = w * 16 + (lane & 7) + ((lane >> 3) & 1) * 8;
    const int a_cb  = ((lane >> 4) & 1) * 4;
    const int b_row = (lane & 7) + ((lane >> 4) & 1) * 8;
    const int b_cb  = ((lane >> 3) & 1) * 4;

    float sacc[6][4];
    #pragma unroll
    for (int nt = 0; nt < 6; nt++)
        #pragma unroll
        for (int i = 0; i < 4; i++) sacc[nt][i] = 0.f;

    #pragma unroll
    for (int kt = 0; kt < 2; kt++) {
        uint32_t qa[4];
        ldsm_x4(qa[0], qa[1], qa[2], qa[3],
                sq + (uint32_t)((a_row * 20 + kt * 8 + a_cb) * 4));
        uint32_t kb[12];
        #pragma unroll
        for (int t = 0; t < 3; t++)
            ldsm_x4(kb[t * 4 + 0], kb[t * 4 + 1], kb[t * 4 + 2], kb[t * 4 + 3],
                    sk + (uint32_t)(((b_row + t * 16) * 20 + kt * 8 + b_cb) * 4));
        #pragma unroll
        for (int nt = 0; nt < 6; nt++)
            mma_bf16(sacc[nt], qa[0], qa[1], qa[2], qa[3], kb[nt * 2], kb[nt * 2 + 1]);
    }

    const float scale = 0.20412414523193154f;
    float m0 = -1e30f, m1 = -1e30f;
    #pragma unroll
    for (int nt = 0; nt < 6; nt++) {
        int j0 = nt * 8 + (lane & 3) * 2;
        float mv0 = mf[p][j0], mv1 = mf[p][j0 + 1];
        sacc[nt][0] = sacc[nt][0] * scale + mv0;
        sacc[nt][1] = sacc[nt][1] * scale + mv1;
        sacc[nt][2] = sacc[nt][2] * scale + mv0;
        sacc[nt][3] = sacc[nt][3] * scale + mv1;
        m0 = fmaxf(m0, fmaxf(sacc[nt][0], sacc[nt][1]));
        m1 = fmaxf(m1, fmaxf(sacc[nt][2], sacc[nt][3]));
    }
    m0 = fmaxf(m0, __shfl_xor_sync(0xFFFFFFFFu, m0, 1));
    m0 = fmaxf(m0, __shfl_xor_sync(0xFFFFFFFFu, m0, 2));
    m1 = fmaxf(m1, __shfl_xor_sync(0xFFFFFFFFu, m1, 1));
    m1 = fmaxf(m1, __shfl_xor_sync(0xFFFFFFFFu, m1, 2));
    float s0 = 0.f, s1 = 0.f;
    #pragma unroll
    for (int nt = 0; nt < 6; nt++) {
        sacc[nt][0] = __expf(sacc[nt][0] - m0);
        sacc[nt][1] = __expf(sacc[nt][1] - m0);
        sacc[nt][2] = __expf(sacc[nt][2] - m1);
        sacc[nt][3] = __expf(sacc[nt][3] - m1);
        s0 += sacc[nt][0] + sacc[nt][1];
        s1 += sacc[nt][2] + sacc[nt][3];
    }
    s0 += __shfl_xor_sync(0xFFFFFFFFu, s0, 1);
    s0 += __shfl_xor_sync(0xFFFFFFFFu, s0, 2);
    s1 += __shfl_xor_sync(0xFFFFFFFFu, s1, 1);
    s1 += __shfl_xor_sync(0xFFFFFFFFu, s1, 2);
    float i0 = 1.f / s0, i1 = 1.f / s1;
    #pragma unroll
    for (int nt = 0; nt < 6; nt++) {
        sacc[nt][0] *= i0; sacc[nt][1] *= i0;
        sacc[nt][2] *= i1; sacc[nt][3] *= i1;
    }

    uint32_t pah[3][4], pal[3][4];
    #pragma unroll
    for (int kt = 0; kt < 3; kt++) {
        const float* t0 = sacc[2 * kt];
        const float* t1 = sacc[2 * kt + 1];
        float src4[4][2] = {{t0[0], t0[1]}, {t0[2], t0[3]}, {t1[0], t1[1]}, {t1[2], t1[3]}};
        #pragma unroll
        for (int r = 0; r < 4; r++) {
            __nv_bfloat162 hh = __floats2bfloat162_rn(src4[r][0], src4[r][1]);
            pah[kt][r] = *reinterpret_cast<const uint32_t*>(&hh);
            float lx = src4[r][0] - __bfloat162float(hh.x);
            float ly = src4[r][1] - __bfloat162float(hh.y);
            pal[kt][r] = pack_bf16(lx, ly);
        }
    }

    float oacc[3][4];
    #pragma unroll
    for (int d = 0; d < 3; d++)
        #pragma unroll
        for (int i = 0; i < 4; i++) oacc[d][i] = 0.f;

    const int v_row = (lane & 7) + ((lane >> 3) & 1) * 8;
    const int v_cb  = ((lane >> 4) & 1) * 4;
    #pragma unroll
    for (int kt = 0; kt < 3; kt++) {
        uint32_t base = svv + (uint32_t)(((16 * kt + v_row) * 20 + v_cb) * 4);
        uint32_t b0[4], b1[4];
        ldsm_x4_t(b0[0], b0[1], b0[2], b0[3], base);
        ldsm_x4_t(b1[0], b1[1], b1[2], b1[3], base + 32);
        mma_bf16(oacc[0], pah[kt][0], pah[kt][1], pah[kt][2], pah[kt][3], b0[0], b0[1]);
        mma_bf16(oacc[0], pal[kt][0], pal[kt][1], pal[kt][2], pal[kt][3], b0[0], b0[1]);
        mma_bf16(oacc[1], pah[kt][0], pah[kt][1], pah[kt][2], pah[kt][3], b0[2], b0[3]);
        mma_bf16(oacc[1], pal[kt][0], pal[kt][1], pal[kt][2], pal[kt][3], b0[2], b0[3]);
        mma_bf16(oacc[2], pah[kt][0], pah[kt][1], pah[kt][2], pah[kt][3], b1[0], b1[1]);
        mma_bf16(oacc[2], pal[kt][0], pal[kt][1], pal[kt][2], pal[kt][3], b1[0], b1[1]);
    }

    {
        size_t r0 = (size_t)s * SETSZ + w * 16 + (lane >> 2);
        int dbase = h * HD + (lane & 3) * 2;
        #pragma unroll
        for (int db = 0; db < 3; db++) {
            int dd = dbase + db * 8;
            *(uint32_t*)&g_ctx[r0 * CDIM + dd]       = pack_bf16(oacc[db][0], oacc[db][1]);
            *(uint32_t*)&g_ctx[(r0 + 8) * CDIM + dd] = pack_bf16(oacc[db][2], oacc[db][3]);
        }
    }
}

// ---------------- launch --------------------------------------------------
extern "C" void kernel_launch(void* const* d_in, const int* in_sizes, int n_in,
                              void* d_out, int out_size)
{
    const float* src   = (const float*)d_in[0];
    const float* pos   = (const float*)d_in[1];
    const float* w_qkv = (const float*)d_in[2];
    const float* b_qkv = (const float*)d_in[3];
    const float* w_out = (const float*)d_in[4];
    const float* b_out = (const float*)d_in[5];
    const float* w1    = (const float*)d_in[6];
    const float* b1    = (const float*)d_in[7];
    const float* w2    = (const float*)d_in[8];
    const float* b2    = (const float*)d_in[9];
    const float* ln1g  = (const float*)d_in[10];
    const float* ln1b  = (const float*)d_in[11];
    const float* ln2g  = (const float*)d_in[12];
    const float* ln2b  = (const float*)d_in[13];
    const float* ln3g  = (const float*)d_in[14];
    const float* ln3b  = (const float*)d_in[15];
    const int*   vidx  = (const int*)d_in[16];
    const uint8_t* msk = (const uint8_t*)d_in[17];
    float* out = (float*)d_out;

    __nv_bfloat16 *p_ctx, *p_xb, *p_h;
    __nv_bfloat16 *p_wqkv, *p_wout, *p_w1, *p_w2;
    cudaGetSymbolAddress((void**)&p_ctx,  g_ctx);
    cudaGetSymbolAddress((void**)&p_xb,   g_xb);
    cudaGetSymbolAddress((void**)&p_h,    g_h);
    cudaGetSymbolAddress((void**)&p_wqkv, g_wqkv);
    cudaGetSymbolAddress((void**)&p_wout, g_wout);
    cudaGetSymbolAddress((void**)&p_w1,   g_w1);
    cudaGetSymbolAddress((void**)&p_w2,   g_w2);

    cudaFuncSetAttribute(qkv_fused,  cudaFuncAttributeMaxDynamicSharedMemorySize, QK_SMEM);
    cudaFuncSetAttribute(oproj_ffn1, cudaFuncAttributeMaxDynamicSharedMemorySize, OP_SMEM);
    cudaFuncSetAttribute(ffn2,       cudaFuncAttributeMaxDynamicSharedMemorySize, F2_SMEM);

    // 0) all weights -> bf16
    {
        int total = CVT_N0 + CVT_N1 + CVT_N2 + CVT_N3;
        cvt_all<<<(total + 255) / 256, 256>>>(w_qkv, w_out, w1, w2);
    }

    const int MB = NVOX / 64;  // 3072

    // 1) fused gather + q,k,v projections
    qkv_fused<<<MB, 256, QK_SMEM>>>(src, pos, vidx, p_wqkv, b_qkv);

    // 2) attention (tensor cores)
    attn_kernel<<<(SETS * NHEAD) / 2, 192>>>(msk);

    // 3) out-proj + LN1 + FFN1 (set-slot order) -> g_xb, g_h
    oproj_ffn1<<<MB, 256, OP_SMEM>>>(p_ctx, p_wout, b_out, vidx, src,
                                     ln1g, ln1b, p_w1, b1);

    // 4) FFN2 + LN2 + residual + LN3, scatter -> out (voxel order, fp32)
    ffn2<<<MB, 256, F2_SMEM>>>(p_h, p_w2, b2, vidx, src, p_xb,
                               ln2g, ln2b, ln3g, ln3b, out);
}